// round 12
// baseline (speedup 1.0000x reference)
#include <cuda_runtime.h>
#include <cuda_bf16.h>
#include <cstdint>

#define B_ 16
#define N_ 1024
#define D_ 768

typedef __nv_bfloat16 bf16;

static const float SCALE_ = 0.03608439182435161f; // 768^-0.5

// ---------------- scratch (device globals: allocation-free contract) ----------------
__device__ __align__(16) float g_S[(size_t)B_ * N_ * N_];   // 64 MB fp32 scores
__device__ __align__(16) float g_Q[(size_t)N_ * N_];        // 4 MB  pos softmax
__device__ __align__(16) bf16 g_xh[(size_t)B_ * N_ * D_];
__device__ __align__(16) bf16 g_yh[(size_t)B_ * N_ * D_], g_yl[(size_t)B_ * N_ * D_];
__device__ __align__(16) bf16 g_wh[(size_t)D_ * D_],      g_wl[(size_t)D_ * D_];
__device__ __align__(16) bf16 g_kh[(size_t)B_ * N_ * D_], g_kl[(size_t)B_ * N_ * D_];
__device__ __align__(16) bf16 g_yth[(size_t)B_ * D_ * N_], g_ytl[(size_t)B_ * D_ * N_];
__device__ __align__(16) bf16 g_ah[(size_t)B_ * N_ * N_],  g_al[(size_t)B_ * N_ * N_];

// ---------------- helpers ----------------
__device__ __forceinline__ uint32_t smem_u32(const void* p) {
    uint32_t a;
    asm("{ .reg .u64 t; cvta.to.shared.u64 t, %1; cvt.u32.u64 %0, t; }" : "=r"(a) : "l"(p));
    return a;
}
#define CP_COMMIT() asm volatile("cp.async.commit_group;" ::: "memory")

__device__ __forceinline__ void mma16816(float* c, const uint32_t* a, const uint32_t* b) {
    asm volatile(
        "mma.sync.aligned.m16n8k16.row.col.f32.bf16.bf16.f32 "
        "{%0,%1,%2,%3}, {%4,%5,%6,%7}, {%8,%9}, {%0,%1,%2,%3};"
        : "+f"(c[0]), "+f"(c[1]), "+f"(c[2]), "+f"(c[3])
        : "r"(a[0]), "r"(a[1]), "r"(a[2]), "r"(a[3]), "r"(b[0]), "r"(b[1]));
}
__device__ __forceinline__ void ldsm4(uint32_t* r, uint32_t addr) {
    asm volatile("ldmatrix.sync.aligned.m8n8.x4.shared.b16 {%0,%1,%2,%3}, [%4];"
        : "=r"(r[0]), "=r"(r[1]), "=r"(r[2]), "=r"(r[3]) : "r"(addr));
}
__device__ __forceinline__ uint32_t pack2(float a, float b) {
    bf16 p[2] = { __float2bfloat16_rn(a), __float2bfloat16_rn(b) };
    return *(uint32_t*)p;
}

// ---------------- HMMA split-bf16 GEMM (FROZEN since R10) ----------------
#define TILE_SZ 8192          // 128 * 64
#define SMEM_BYTES 98304      // 96 KB (both variants)

__device__ __forceinline__ void fill_tile(uint32_t dst, const bf16* __restrict__ g,
                                          int ld, int r0, int k0, int tid) {
#pragma unroll
    for (int it = 0; it < 4; it++) {
        int idx = it * 128 + tid;
        int r = idx >> 2, b = idx & 3;
        uint32_t sw = (uint32_t)(r * 64 + ((b ^ ((r >> 1) & 3)) * 16));
        const bf16* src = g + (size_t)(r0 + r) * ld + k0 + b * 8;
        asm volatile("cp.async.cg.shared.global [%0], [%1], 16;"
                     :: "r"(dst + sw), "l"(src));
    }
}

template <int TERMS>
__device__ __forceinline__ void fill_chunk(uint32_t S0,
                                           const bf16* Ah_, const bf16* Al_,
                                           const bf16* Bh_, const bf16* Bl_,
                                           int lda, int ldb, int m0, int n0, int k0, int tid) {
    constexpr int BH = (TERMS == 3) ? 2 : 1;
    fill_tile(S0 + 0 * TILE_SZ, Ah_, lda, m0, k0, tid);
    if (TERMS == 3) fill_tile(S0 + 1 * TILE_SZ, Al_, lda, m0, k0, tid);
    fill_tile(S0 + BH * TILE_SZ,       Bh_, ldb, n0, k0, tid);
    fill_tile(S0 + (BH + 1) * TILE_SZ, Bl_, ldb, n0, k0, tid);
}

template <bool SPLIT_OUT, int TERMS>
__global__ void __launch_bounds__(128, 2) gemm_mma(
    const bf16* __restrict__ Ah_, const bf16* __restrict__ Al_,
    const bf16* __restrict__ Bh_, const bf16* __restrict__ Bl_,
    float* __restrict__ C, bf16* __restrict__ Ch, bf16* __restrict__ Cl,
    int K, int lda, int ldb, int ldc,
    size_t sA, size_t sB, size_t sC, float alpha)
{
    constexpr int NST = (TERMS == 3) ? 3 : 4;
    constexpr int STG = ((TERMS == 3) ? 4 : 3) * TILE_SZ;
    constexpr int BH  = (TERMS == 3) ? 2 : 1;

    extern __shared__ char sm[];
    const uint32_t sb = smem_u32(sm);
    const int tid = threadIdx.x, lane = tid & 31, w = tid >> 5;
    const int wm = w & 1, wn = w >> 1;
    const int g = lane >> 2, tig = lane & 3;
    const int m0 = blockIdx.y * 128, n0 = blockIdx.x * 128;

    Ah_ += (size_t)blockIdx.z * sA; Al_ += (size_t)blockIdx.z * sA;
    Bh_ += (size_t)blockIdx.z * sB; Bl_ += (size_t)blockIdx.z * sB;

    const int rowA = wm * 64 + (lane & 7) + (lane & 8);
    const int hA = (lane >> 4) & 1;
    const int xA = (rowA >> 1) & 3;
    const uint32_t aRow = (uint32_t)(rowA * 64);
    const uint32_t aBlk0 = (uint32_t)(((0 + hA) ^ xA) * 16);
    const uint32_t aBlk1 = (uint32_t)(((2 + hA) ^ xA) * 16);
    const int rowB = wn * 64 + (lane & 7) + ((lane & 16) >> 1);
    const int hB = (lane >> 3) & 1;
    const int xB = (rowB >> 1) & 3;
    const uint32_t bRow = (uint32_t)(rowB * 64);
    const uint32_t bBlk0 = (uint32_t)(((0 + hB) ^ xB) * 16);
    const uint32_t bBlk1 = (uint32_t)(((2 + hB) ^ xB) * 16);

    float acc[4][8][4];
#pragma unroll
    for (int i = 0; i < 4; i++)
#pragma unroll
        for (int j = 0; j < 8; j++)
#pragma unroll
            for (int c = 0; c < 4; c++) acc[i][j][c] = 0.f;

    const int KT = K >> 5;

#pragma unroll
    for (int p = 0; p < NST; p++) {
        fill_chunk<TERMS>(sb + p * STG, Ah_, Al_, Bh_, Bl_, lda, ldb, m0, n0, p * 32, tid);
        CP_COMMIT();
    }

    for (int kt = 0; kt < KT; ++kt) {
        asm volatile("cp.async.wait_group %0;" :: "n"(NST - 2) : "memory");
        __syncthreads();
        const uint32_t S0 = sb + (kt % NST) * STG;
        const uint32_t pAh = S0, pAl = S0 + TILE_SZ;
        const uint32_t pBh = S0 + BH * TILE_SZ, pBl = S0 + (BH + 1) * TILE_SZ;

        uint32_t ah[4][4], al[4][4], bh[8][2], bl[8][2];
#pragma unroll
        for (int mf = 0; mf < 4; mf++) {
            ldsm4(&ah[mf][0], pAh + aRow + mf * 1024 + aBlk0);
            if (TERMS == 3) ldsm4(&al[mf][0], pAl + aRow + mf * 1024 + aBlk0);
        }
#pragma unroll
        for (int p = 0; p < 4; p++) {
            ldsm4(&bh[2 * p][0], pBh + bRow + p * 1024 + bBlk0);
            ldsm4(&bl[2 * p][0], pBl + bRow + p * 1024 + bBlk0);
        }
        if (kt >= 1) {
            if (kt + NST - 1 < KT)
                fill_chunk<TERMS>(sb + ((kt + NST - 1) % NST) * STG,
                                  Ah_, Al_, Bh_, Bl_, lda, ldb, m0, n0,
                                  (kt + NST - 1) * 32, tid);
            CP_COMMIT();
        }
#pragma unroll
        for (int mf = 0; mf < 4; mf++)
#pragma unroll
            for (int nf = 0; nf < 8; nf++)
                mma16816(acc[mf][nf], ah[mf], bh[nf]);
#pragma unroll
        for (int mf = 0; mf < 4; mf++)
#pragma unroll
            for (int nf = 0; nf < 8; nf++)
                mma16816(acc[mf][nf], ah[mf], bl[nf]);
        if (TERMS == 3) {
#pragma unroll
            for (int mf = 0; mf < 4; mf++)
#pragma unroll
                for (int nf = 0; nf < 8; nf++)
                    mma16816(acc[mf][nf], al[mf], bh[nf]);
        }

#pragma unroll
        for (int mf = 0; mf < 4; mf++) {
            ldsm4(&ah[mf][0], pAh + aRow + mf * 1024 + aBlk1);
            if (TERMS == 3) ldsm4(&al[mf][0], pAl + aRow + mf * 1024 + aBlk1);
        }
#pragma unroll
        for (int p = 0; p < 4; p++) {
            ldsm4(&bh[2 * p][0], pBh + bRow + p * 1024 + bBlk1);
            ldsm4(&bl[2 * p][0], pBl + bRow + p * 1024 + bBlk1);
        }
#pragma unroll
        for (int mf = 0; mf < 4; mf++)
#pragma unroll
            for (int nf = 0; nf < 8; nf++)
                mma16816(acc[mf][nf], ah[mf], bh[nf]);
#pragma unroll
        for (int mf = 0; mf < 4; mf++)
#pragma unroll
            for (int nf = 0; nf < 8; nf++)
                mma16816(acc[mf][nf], ah[mf], bl[nf]);
        if (TERMS == 3) {
#pragma unroll
            for (int mf = 0; mf < 4; mf++)
#pragma unroll
                for (int nf = 0; nf < 8; nf++)
                    mma16816(acc[mf][nf], al[mf], bh[nf]);
        }
    }

    // epilogue
#pragma unroll
    for (int mf = 0; mf < 4; mf++) {
#pragma unroll
        for (int nf = 0; nf < 8; nf++) {
            const int row = m0 + wm * 64 + mf * 16 + g;
            const int col = n0 + wn * 64 + nf * 8 + tig * 2;
            float c0 = acc[mf][nf][0] * alpha, c1 = acc[mf][nf][1] * alpha;
            float c2 = acc[mf][nf][2] * alpha, c3 = acc[mf][nf][3] * alpha;
            if (SPLIT_OUT) {
                bf16 h0 = __float2bfloat16_rn(c0), h1 = __float2bfloat16_rn(c1);
                bf16 h2 = __float2bfloat16_rn(c2), h3 = __float2bfloat16_rn(c3);
                bf16 l0 = __float2bfloat16_rn(c0 - __bfloat162float(h0));
                bf16 l1 = __float2bfloat16_rn(c1 - __bfloat162float(h1));
                bf16 l2 = __float2bfloat16_rn(c2 - __bfloat162float(h2));
                bf16 l3 = __float2bfloat16_rn(c3 - __bfloat162float(h3));
                bf16 ph0[2] = {h0, h1}, ph2[2] = {h2, h3};
                bf16 pl0[2] = {l0, l1}, pl2[2] = {l2, l3};
                *(uint32_t*)&Ch[(size_t)row * ldc + col]       = *(uint32_t*)ph0;
                *(uint32_t*)&Ch[(size_t)(row + 8) * ldc + col] = *(uint32_t*)ph2;
                *(uint32_t*)&Cl[(size_t)row * ldc + col]       = *(uint32_t*)pl0;
                *(uint32_t*)&Cl[(size_t)(row + 8) * ldc + col] = *(uint32_t*)pl2;
            } else {
                float* Cp = C + (size_t)blockIdx.z * sC;
                float2 v0 = {c0, c1}, v2 = {c2, c3};
                *(float2*)&Cp[(size_t)row * ldc + col]       = v0;
                *(float2*)&Cp[(size_t)(row + 8) * ldc + col] = v2;
            }
        }
    }
}

// ---------------- fp32 -> (hi,lo) bf16 split ----------------
__global__ void __launch_bounds__(256) split_k(const float4* __restrict__ in,
                                               uint2* __restrict__ hi, uint2* __restrict__ lo,
                                               int n4) {
    int i = blockIdx.x * 256 + threadIdx.x;
    if (i >= n4) return;
    float4 v = in[i];
    float xs[4] = {v.x, v.y, v.z, v.w};
    bf16 h[4], l[4];
#pragma unroll
    for (int j = 0; j < 4; j++) {
        h[j] = __float2bfloat16_rn(xs[j]);
        l[j] = __float2bfloat16_rn(xs[j] - __bfloat162float(h[j]));
    }
    hi[i] = *(uint2*)h;
    lo[i] = *(uint2*)l;
}

// ---------------- fp32 -> hi bf16 only ----------------
__global__ void __launch_bounds__(256) split_h(const float4* __restrict__ in,
                                               uint2* __restrict__ hi, int n4) {
    int i = blockIdx.x * 256 + threadIdx.x;
    if (i >= n4) return;
    float4 v = in[i];
    float xs[4] = {v.x, v.y, v.z, v.w};
    bf16 h[4];
#pragma unroll
    for (int j = 0; j < 4; j++) h[j] = __float2bfloat16_rn(xs[j]);
    hi[i] = *(uint2*)h;
}

// ------- y [B,N,D]: split hi/lo AND transposed hi/lo, packed-pair stores -------
// 64x64 tile, block (32,8). All bf16 stores are uint32 pairs (128B transactions).
__global__ void __launch_bounds__(256) split_Ty(const float* __restrict__ y,
                                                bf16* __restrict__ yh, bf16* __restrict__ yl,
                                                bf16* __restrict__ th, bf16* __restrict__ tl) {
    __shared__ float t[64][65];
    const int b = blockIdx.z;
    const float* Y = y + (size_t)b * N_ * D_;
    const int n0 = blockIdx.x * 64, d0 = blockIdx.y * 64;
    const int tx = threadIdx.x, ty = threadIdx.y;  // (32, 8)
    bf16* YH = yh + (size_t)b * N_ * D_;
    bf16* YL = yl + (size_t)b * N_ * D_;
#pragma unroll
    for (int i = 0; i < 8; i++) {
        const int r = i * 8 + ty;                  // n within tile
        float2 v = *(const float2*)&Y[(size_t)(n0 + r) * D_ + d0 + 2 * tx];
        t[r][2 * tx] = v.x; t[r][2 * tx + 1] = v.y;
        bf16 h0 = __float2bfloat16_rn(v.x), h1 = __float2bfloat16_rn(v.y);
        float l0 = v.x - __bfloat162float(h0), l1 = v.y - __bfloat162float(h1);
        bf16 ph[2] = {h0, h1};
        *(uint32_t*)&YH[(size_t)(n0 + r) * D_ + d0 + 2 * tx] = *(uint32_t*)ph;
        *(uint32_t*)&YL[(size_t)(n0 + r) * D_ + d0 + 2 * tx] = pack2(l0, l1);
    }
    __syncthreads();
    bf16* TH = th + (size_t)b * D_ * N_;
    bf16* TL = tl + (size_t)b * D_ * N_;
#pragma unroll
    for (int i = 0; i < 8; i++) {
        const int c = i * 8 + ty;                  // d within tile
        float v0 = t[2 * tx][c], v1 = t[2 * tx + 1][c];
        bf16 h0 = __float2bfloat16_rn(v0), h1 = __float2bfloat16_rn(v1);
        float l0 = v0 - __bfloat162float(h0), l1 = v1 - __bfloat162float(h1);
        bf16 ph[2] = {h0, h1};
        *(uint32_t*)&TH[(size_t)(d0 + c) * N_ + n0 + 2 * tx] = *(uint32_t*)ph;
        *(uint32_t*)&TL[(size_t)(d0 + c) * N_ + n0 + 2 * tx] = pack2(l0, l1);
    }
}

// ---------------- reductions ----------------
__device__ __forceinline__ float warpMax(float v) {
#pragma unroll
    for (int o = 16; o; o >>= 1) v = fmaxf(v, __shfl_xor_sync(0xffffffffu, v, o));
    return v;
}
__device__ __forceinline__ float warpSum(float v) {
#pragma unroll
    for (int o = 16; o; o >>= 1) v += __shfl_xor_sync(0xffffffffu, v, o);
    return v;
}

// ---------------- positional softmax ----------------
__global__ void __launch_bounds__(256) pos_kernel(
    const float* __restrict__ coords, const float* __restrict__ pe, float* __restrict__ Q)
{
    __shared__ float pesh[6];
    __shared__ float red[8], red2[8];
    const int p = blockIdx.x;
    const int tid = threadIdx.x;
    if (tid < 6) pesh[tid] = pe[p * 6 + tid];
    __syncthreads();

    const float* cbase = coords + (size_t)p * N_ * 6;
    float z[4];
#pragma unroll
    for (int i = 0; i < 4; i++) {
        const float* c = cbase + (size_t)(i * 256 + tid) * 6;
        float2 c01 = *(const float2*)(c);
        float2 c23 = *(const float2*)(c + 2);
        float2 c45 = *(const float2*)(c + 4);
        z[i] = c01.x * pesh[0] + c01.y * pesh[1] + c23.x * pesh[2]
             + c23.y * pesh[3] + c45.x * pesh[4] + c45.y * pesh[5];
    }
    float m = fmaxf(fmaxf(z[0], z[1]), fmaxf(z[2], z[3]));
    m = warpMax(m);
    if ((tid & 31) == 0) red[tid >> 5] = m;
    __syncthreads();
    m = red[0];
#pragma unroll
    for (int i = 1; i < 8; i++) m = fmaxf(m, red[i]);

    float e[4], s = 0.f;
#pragma unroll
    for (int i = 0; i < 4; i++) { e[i] = __expf(z[i] - m); s += e[i]; }
    s = warpSum(s);
    if ((tid & 31) == 0) red2[tid >> 5] = s;
    __syncthreads();
    s = red2[0];
#pragma unroll
    for (int i = 1; i < 8; i++) s += red2[i];
    const float inv = 1.f / s;
#pragma unroll
    for (int i = 0; i < 4; i++)
        Q[(size_t)p * N_ + i * 256 + tid] = e[i] * inv;
}

// ---- row softmax + gate mix + entropy; warp per (b,n); Q[n] staged in SMEM ----
// grid (N_, B_/8), block 256: 8 warps = 8 batches sharing one n.
__global__ void __launch_bounds__(256) mix_kernel(
    const float* __restrict__ S, const float* __restrict__ Q,
    const float* __restrict__ gating, const float* __restrict__ temp,
    bf16* __restrict__ AH, bf16* __restrict__ AL, float* __restrict__ hmap)
{
    __shared__ float qs[N_];           // 4 KB: Q row shared by all 8 warps
    const int n = blockIdx.x;
    const int tid = threadIdx.x, lane = tid & 31;
    const int b = blockIdx.y * 8 + (tid >> 5);
    const int row = b * N_ + n;

    for (int i = tid; i < N_ / 4; i += 256)
        ((float4*)qs)[i] = ((const float4*)(Q + (size_t)n * N_))[i];
    __syncthreads();

    const float4* s4 = (const float4*)(S + (size_t)row * N_);
    const float4* q4 = (const float4*)qs;

    float4 v[8];
#pragma unroll
    for (int i = 0; i < 8; i++) v[i] = s4[lane + 32 * i];

    float m = -1e30f;
#pragma unroll
    for (int i = 0; i < 8; i++)
        m = fmaxf(m, fmaxf(fmaxf(v[i].x, v[i].y), fmaxf(v[i].z, v[i].w)));
    m = warpMax(m);

    float ssum = 0.f;
#pragma unroll
    for (int i = 0; i < 8; i++) {
        v[i].x = __expf(v[i].x - m); v[i].y = __expf(v[i].y - m);
        v[i].z = __expf(v[i].z - m); v[i].w = __expf(v[i].w - m);
        ssum += v[i].x + v[i].y + v[i].z + v[i].w;
    }
    ssum = warpSum(ssum);
    const float inv = 1.f / ssum;

    const float gt = 1.f / (1.f + __expf(-gating[0]));
    const float og = 1.f - gt;

    uint2* AH2 = (uint2*)(AH + (size_t)row * N_);
    uint2* AL2 = (uint2*)(AL + (size_t)row * N_);
    float H = 0.f;
#pragma unroll
    for (int i = 0; i < 8; i++) {
        float4 qv = q4[lane + 32 * i];
        float a[4];
        a[0] = og * v[i].x * inv + gt * qv.x;
        a[1] = og * v[i].y * inv + gt * qv.y;
        a[2] = og * v[i].z * inv + gt * qv.z;
        a[3] = og * v[i].w * inv + gt * qv.w;
        H -= a[0] * __logf(a[0] + 1e-8f) + a[1] * __logf(a[1] + 1e-8f)
           + a[2] * __logf(a[2] + 1e-8f) + a[3] * __logf(a[3] + 1e-8f);
        bf16 h[4], l[4];
#pragma unroll
        for (int j = 0; j < 4; j++) {
            h[j] = __float2bfloat16_rn(a[j]);
            l[j] = __float2bfloat16_rn(a[j] - __bfloat162float(h[j]));
        }
        AH2[lane + 32 * i] = *(uint2*)h;
        AL2[lane + 32 * i] = *(uint2*)l;
    }
    H = warpSum(H);
    if (lane == 0) {
        const float sig = 1.f / (1.f + __expf(-temp[0] * H));
        hmap[row] = 2.f * (1.f - sig);
    }
}

// ---------------- launch ----------------
extern "C" void kernel_launch(void* const* d_in, const int* in_sizes, int n_in,
                              void* d_out, int out_size)
{
    const float* x      = (const float*)d_in[0];
    const float* y      = (const float*)d_in[1];
    const float* coords = (const float*)d_in[2];
    const float* W      = (const float*)d_in[3];
    const float* pe     = (const float*)d_in[4];
    const float* gating = (const float*)d_in[5];
    const float* temp   = (const float*)d_in[6];

    float* out  = (float*)d_out;                // [B,N,D]
    float* hmap = out + (size_t)B_ * N_ * D_;   // [B,N,1]

    float *Sb, *Qb;
    bf16 *xh, *yh, *yl, *wh, *wl, *kh, *kl, *yth, *ytl, *ah, *al;
    cudaGetSymbolAddress((void**)&Sb, g_S);
    cudaGetSymbolAddress((void**)&Qb, g_Q);
    cudaGetSymbolAddress((void**)&xh, g_xh);
    cudaGetSymbolAddress((void**)&yh, g_yh);  cudaGetSymbolAddress((void**)&yl, g_yl);
    cudaGetSymbolAddress((void**)&wh, g_wh);  cudaGetSymbolAddress((void**)&wl, g_wl);
    cudaGetSymbolAddress((void**)&kh, g_kh);  cudaGetSymbolAddress((void**)&kl, g_kl);
    cudaGetSymbolAddress((void**)&yth, g_yth); cudaGetSymbolAddress((void**)&ytl, g_ytl);
    cudaGetSymbolAddress((void**)&ah, g_ah);  cudaGetSymbolAddress((void**)&al, g_al);

    cudaFuncSetAttribute((const void*)gemm_mma<true, 3>,  cudaFuncAttributeMaxDynamicSharedMemorySize, SMEM_BYTES);
    cudaFuncSetAttribute((const void*)gemm_mma<false, 2>, cudaFuncAttributeMaxDynamicSharedMemorySize, SMEM_BYTES);
    cudaFuncSetAttribute((const void*)gemm_mma<false, 3>, cudaFuncAttributeMaxDynamicSharedMemorySize, SMEM_BYTES);

    const int nBND4 = (B_ * N_ * D_) / 4;
    const int nDD4  = (D_ * D_) / 4;

    split_Ty<<<dim3(N_ / 64, D_ / 64, B_), dim3(32, 8)>>>(y, yh, yl, yth, ytl);
    split_h<<<(nBND4 + 255) / 256, 256>>>((const float4*)x, (uint2*)xh, nBND4);
    split_k<<<(nDD4  + 255) / 256, 256>>>((const float4*)W, (uint2*)wh, (uint2*)wl, nDD4);

    pos_kernel<<<N_, 256>>>(coords, pe, Qb);

    // 1) k = y @ W^T  (M=16384, N=768, K=768) -> kh/kl bf16 directly (3-term)
    gemm_mma<true, 3><<<dim3(D_ / 128, (B_ * N_) / 128, 1), 128, SMEM_BYTES>>>(
        yh, yl, wh, wl, nullptr, kh, kl, D_, D_, D_, D_, 0, 0, 0, 1.0f);

    // 2) S = (x @ k^T) * SCALE, batched over B -> fp32 (2-term)
    gemm_mma<false, 2><<<dim3(N_ / 128, N_ / 128, B_), 128, SMEM_BYTES>>>(
        xh, xh, kh, kl, Sb, nullptr, nullptr, D_, D_, D_, N_,
        (size_t)N_ * D_, (size_t)N_ * D_, (size_t)N_ * N_, SCALE_);

    // 3) softmax + mix + entropy -> attn bf16 hi/lo + hmap (Q staged in SMEM)
    mix_kernel<<<dim3(N_, B_ / 8), 256>>>(Sb, Qb, gating, temp, ah, al, hmap);

    // 4) out = attn @ y (B operand = y^T per batch, K=1024) (3-term)
    gemm_mma<false, 3><<<dim3(D_ / 128, N_ / 128, B_), 128, SMEM_BYTES>>>(
        ah, al, yth, ytl, out, nullptr, nullptr, N_, N_, N_, D_,
        (size_t)N_ * N_, (size_t)D_ * N_, (size_t)N_ * D_, 1.0f);
}

// round 13
// speedup vs baseline: 1.4880x; 1.4880x over previous
#include <cuda_runtime.h>
#include <cuda_bf16.h>
#include <cstdint>

#define B_ 16
#define N_ 1024
#define D_ 768

typedef __nv_bfloat16 bf16;

static const float SCALE_ = 0.03608439182435161f; // 768^-0.5

// ---------------- scratch (device globals: allocation-free contract) ----------------
__device__ __align__(16) float g_S[(size_t)B_ * N_ * N_];   // 64 MB fp32 scores
__device__ __align__(16) float g_Q[(size_t)N_ * N_];        // 4 MB  pos softmax
__device__ __align__(16) bf16 g_xh[(size_t)B_ * N_ * D_];
__device__ __align__(16) bf16 g_yh[(size_t)B_ * N_ * D_], g_yl[(size_t)B_ * N_ * D_];
__device__ __align__(16) bf16 g_wh[(size_t)D_ * D_],      g_wl[(size_t)D_ * D_];
__device__ __align__(16) bf16 g_kh[(size_t)B_ * N_ * D_], g_kl[(size_t)B_ * N_ * D_];
__device__ __align__(16) bf16 g_yth[(size_t)B_ * D_ * N_], g_ytl[(size_t)B_ * D_ * N_];
__device__ __align__(16) bf16 g_ah[(size_t)B_ * N_ * N_],  g_al[(size_t)B_ * N_ * N_];

// ---------------- helpers ----------------
__device__ __forceinline__ uint32_t smem_u32(const void* p) {
    uint32_t a;
    asm("{ .reg .u64 t; cvta.to.shared.u64 t, %1; cvt.u32.u64 %0, t; }" : "=r"(a) : "l"(p));
    return a;
}
#define CP_COMMIT() asm volatile("cp.async.commit_group;" ::: "memory")

__device__ __forceinline__ void mma16816(float* c, const uint32_t* a, const uint32_t* b) {
    asm volatile(
        "mma.sync.aligned.m16n8k16.row.col.f32.bf16.bf16.f32 "
        "{%0,%1,%2,%3}, {%4,%5,%6,%7}, {%8,%9}, {%0,%1,%2,%3};"
        : "+f"(c[0]), "+f"(c[1]), "+f"(c[2]), "+f"(c[3])
        : "r"(a[0]), "r"(a[1]), "r"(a[2]), "r"(a[3]), "r"(b[0]), "r"(b[1]));
}
__device__ __forceinline__ void ldsm4(uint32_t* r, uint32_t addr) {
    asm volatile("ldmatrix.sync.aligned.m8n8.x4.shared.b16 {%0,%1,%2,%3}, [%4];"
        : "=r"(r[0]), "=r"(r[1]), "=r"(r[2]), "=r"(r[3]) : "r"(addr));
}

// ---------------- HMMA split-bf16 GEMM (FROZEN since R10) ----------------
#define TILE_SZ 8192          // 128 * 64
#define SMEM_BYTES 98304      // 96 KB (both variants)

__device__ __forceinline__ void fill_tile(uint32_t dst, const bf16* __restrict__ g,
                                          int ld, int r0, int k0, int tid) {
#pragma unroll
    for (int it = 0; it < 4; it++) {
        int idx = it * 128 + tid;
        int r = idx >> 2, b = idx & 3;
        uint32_t sw = (uint32_t)(r * 64 + ((b ^ ((r >> 1) & 3)) * 16));
        const bf16* src = g + (size_t)(r0 + r) * ld + k0 + b * 8;
        asm volatile("cp.async.cg.shared.global [%0], [%1], 16;"
                     :: "r"(dst + sw), "l"(src));
    }
}

template <int TERMS>
__device__ __forceinline__ void fill_chunk(uint32_t S0,
                                           const bf16* Ah_, const bf16* Al_,
                                           const bf16* Bh_, const bf16* Bl_,
                                           int lda, int ldb, int m0, int n0, int k0, int tid) {
    constexpr int BH = (TERMS == 3) ? 2 : 1;
    fill_tile(S0 + 0 * TILE_SZ, Ah_, lda, m0, k0, tid);
    if (TERMS == 3) fill_tile(S0 + 1 * TILE_SZ, Al_, lda, m0, k0, tid);
    fill_tile(S0 + BH * TILE_SZ,       Bh_, ldb, n0, k0, tid);
    fill_tile(S0 + (BH + 1) * TILE_SZ, Bl_, ldb, n0, k0, tid);
}

template <bool SPLIT_OUT, int TERMS>
__global__ void __launch_bounds__(128, 2) gemm_mma(
    const bf16* __restrict__ Ah_, const bf16* __restrict__ Al_,
    const bf16* __restrict__ Bh_, const bf16* __restrict__ Bl_,
    float* __restrict__ C, bf16* __restrict__ Ch, bf16* __restrict__ Cl,
    int K, int lda, int ldb, int ldc,
    size_t sA, size_t sB, size_t sC, float alpha)
{
    constexpr int NST = (TERMS == 3) ? 3 : 4;
    constexpr int STG = ((TERMS == 3) ? 4 : 3) * TILE_SZ;
    constexpr int BH  = (TERMS == 3) ? 2 : 1;

    extern __shared__ char sm[];
    const uint32_t sb = smem_u32(sm);
    const int tid = threadIdx.x, lane = tid & 31, w = tid >> 5;
    const int wm = w & 1, wn = w >> 1;
    const int g = lane >> 2, tig = lane & 3;
    const int m0 = blockIdx.y * 128, n0 = blockIdx.x * 128;

    Ah_ += (size_t)blockIdx.z * sA; Al_ += (size_t)blockIdx.z * sA;
    Bh_ += (size_t)blockIdx.z * sB; Bl_ += (size_t)blockIdx.z * sB;

    const int rowA = wm * 64 + (lane & 7) + (lane & 8);
    const int hA = (lane >> 4) & 1;
    const int xA = (rowA >> 1) & 3;
    const uint32_t aRow = (uint32_t)(rowA * 64);
    const uint32_t aBlk0 = (uint32_t)(((0 + hA) ^ xA) * 16);
    const uint32_t aBlk1 = (uint32_t)(((2 + hA) ^ xA) * 16);
    const int rowB = wn * 64 + (lane & 7) + ((lane & 16) >> 1);
    const int hB = (lane >> 3) & 1;
    const int xB = (rowB >> 1) & 3;
    const uint32_t bRow = (uint32_t)(rowB * 64);
    const uint32_t bBlk0 = (uint32_t)(((0 + hB) ^ xB) * 16);
    const uint32_t bBlk1 = (uint32_t)(((2 + hB) ^ xB) * 16);

    float acc[4][8][4];
#pragma unroll
    for (int i = 0; i < 4; i++)
#pragma unroll
        for (int j = 0; j < 8; j++)
#pragma unroll
            for (int c = 0; c < 4; c++) acc[i][j][c] = 0.f;

    const int KT = K >> 5;

#pragma unroll
    for (int p = 0; p < NST; p++) {
        fill_chunk<TERMS>(sb + p * STG, Ah_, Al_, Bh_, Bl_, lda, ldb, m0, n0, p * 32, tid);
        CP_COMMIT();
    }

    for (int kt = 0; kt < KT; ++kt) {
        asm volatile("cp.async.wait_group %0;" :: "n"(NST - 2) : "memory");
        __syncthreads();
        const uint32_t S0 = sb + (kt % NST) * STG;
        const uint32_t pAh = S0, pAl = S0 + TILE_SZ;
        const uint32_t pBh = S0 + BH * TILE_SZ, pBl = S0 + (BH + 1) * TILE_SZ;

        uint32_t ah[4][4], al[4][4], bh[8][2], bl[8][2];
#pragma unroll
        for (int mf = 0; mf < 4; mf++) {
            ldsm4(&ah[mf][0], pAh + aRow + mf * 1024 + aBlk0);
            if (TERMS == 3) ldsm4(&al[mf][0], pAl + aRow + mf * 1024 + aBlk0);
        }
#pragma unroll
        for (int p = 0; p < 4; p++) {
            ldsm4(&bh[2 * p][0], pBh + bRow + p * 1024 + bBlk0);
            ldsm4(&bl[2 * p][0], pBl + bRow + p * 1024 + bBlk0);
        }
        if (kt >= 1) {
            if (kt + NST - 1 < KT)
                fill_chunk<TERMS>(sb + ((kt + NST - 1) % NST) * STG,
                                  Ah_, Al_, Bh_, Bl_, lda, ldb, m0, n0,
                                  (kt + NST - 1) * 32, tid);
            CP_COMMIT();
        }
#pragma unroll
        for (int mf = 0; mf < 4; mf++)
#pragma unroll
            for (int nf = 0; nf < 8; nf++)
                mma16816(acc[mf][nf], ah[mf], bh[nf]);
#pragma unroll
        for (int mf = 0; mf < 4; mf++)
#pragma unroll
            for (int nf = 0; nf < 8; nf++)
                mma16816(acc[mf][nf], ah[mf], bl[nf]);
        if (TERMS == 3) {
#pragma unroll
            for (int mf = 0; mf < 4; mf++)
#pragma unroll
                for (int nf = 0; nf < 8; nf++)
                    mma16816(acc[mf][nf], al[mf], bh[nf]);
        }

#pragma unroll
        for (int mf = 0; mf < 4; mf++) {
            ldsm4(&ah[mf][0], pAh + aRow + mf * 1024 + aBlk1);
            if (TERMS == 3) ldsm4(&al[mf][0], pAl + aRow + mf * 1024 + aBlk1);
        }
#pragma unroll
        for (int p = 0; p < 4; p++) {
            ldsm4(&bh[2 * p][0], pBh + bRow + p * 1024 + bBlk1);
            ldsm4(&bl[2 * p][0], pBl + bRow + p * 1024 + bBlk1);
        }
#pragma unroll
        for (int mf = 0; mf < 4; mf++)
#pragma unroll
            for (int nf = 0; nf < 8; nf++)
                mma16816(acc[mf][nf], ah[mf], bh[nf]);
#pragma unroll
        for (int mf = 0; mf < 4; mf++)
#pragma unroll
            for (int nf = 0; nf < 8; nf++)
                mma16816(acc[mf][nf], ah[mf], bl[nf]);
        if (TERMS == 3) {
#pragma unroll
            for (int mf = 0; mf < 4; mf++)
#pragma unroll
                for (int nf = 0; nf < 8; nf++)
                    mma16816(acc[mf][nf], al[mf], bh[nf]);
        }
    }

    // epilogue
#pragma unroll
    for (int mf = 0; mf < 4; mf++) {
#pragma unroll
        for (int nf = 0; nf < 8; nf++) {
            const int row = m0 + wm * 64 + mf * 16 + g;
            const int col = n0 + wn * 64 + nf * 8 + tig * 2;
            float c0 = acc[mf][nf][0] * alpha, c1 = acc[mf][nf][1] * alpha;
            float c2 = acc[mf][nf][2] * alpha, c3 = acc[mf][nf][3] * alpha;
            if (SPLIT_OUT) {
                bf16 h0 = __float2bfloat16_rn(c0), h1 = __float2bfloat16_rn(c1);
                bf16 h2 = __float2bfloat16_rn(c2), h3 = __float2bfloat16_rn(c3);
                bf16 l0 = __float2bfloat16_rn(c0 - __bfloat162float(h0));
                bf16 l1 = __float2bfloat16_rn(c1 - __bfloat162float(h1));
                bf16 l2 = __float2bfloat16_rn(c2 - __bfloat162float(h2));
                bf16 l3 = __float2bfloat16_rn(c3 - __bfloat162float(h3));
                bf16 ph0[2] = {h0, h1}, ph2[2] = {h2, h3};
                bf16 pl0[2] = {l0, l1}, pl2[2] = {l2, l3};
                *(uint32_t*)&Ch[(size_t)row * ldc + col]       = *(uint32_t*)ph0;
                *(uint32_t*)&Ch[(size_t)(row + 8) * ldc + col] = *(uint32_t*)ph2;
                *(uint32_t*)&Cl[(size_t)row * ldc + col]       = *(uint32_t*)pl0;
                *(uint32_t*)&Cl[(size_t)(row + 8) * ldc + col] = *(uint32_t*)pl2;
            } else {
                float* Cp = C + (size_t)blockIdx.z * sC;
                float2 v0 = {c0, c1}, v2 = {c2, c3};
                *(float2*)&Cp[(size_t)row * ldc + col]       = v0;
                *(float2*)&Cp[(size_t)(row + 8) * ldc + col] = v2;
            }
        }
    }
}

// ---------------- fp32 -> (hi,lo) bf16 split ----------------
__global__ void __launch_bounds__(256) split_k(const float4* __restrict__ in,
                                               uint2* __restrict__ hi, uint2* __restrict__ lo,
                                               int n4) {
    int i = blockIdx.x * 256 + threadIdx.x;
    if (i >= n4) return;
    float4 v = in[i];
    float xs[4] = {v.x, v.y, v.z, v.w};
    bf16 h[4], l[4];
#pragma unroll
    for (int j = 0; j < 4; j++) {
        h[j] = __float2bfloat16_rn(xs[j]);
        l[j] = __float2bfloat16_rn(xs[j] - __bfloat162float(h[j]));
    }
    hi[i] = *(uint2*)h;
    lo[i] = *(uint2*)l;
}

// ---------------- fp32 -> hi bf16 only ----------------
__global__ void __launch_bounds__(256) split_h(const float4* __restrict__ in,
                                               uint2* __restrict__ hi, int n4) {
    int i = blockIdx.x * 256 + threadIdx.x;
    if (i >= n4) return;
    float4 v = in[i];
    float xs[4] = {v.x, v.y, v.z, v.w};
    bf16 h[4];
#pragma unroll
    for (int j = 0; j < 4; j++) h[j] = __float2bfloat16_rn(xs[j]);
    hi[i] = *(uint2*)h;
}

// ------- y [B,N,D]: split to yh/yl AND transposed yth/ytl [B,D,N] in one pass -------
// (R11 proven version: 32x32 tile)
__global__ void __launch_bounds__(256) split_Ty(const float* __restrict__ y,
                                                bf16* __restrict__ yh, bf16* __restrict__ yl,
                                                bf16* __restrict__ th, bf16* __restrict__ tl) {
    __shared__ float t[32][33];
    const int b = blockIdx.z;
    const float* Y = y + (size_t)b * N_ * D_;
    const int n0 = blockIdx.x * 32, d0 = blockIdx.y * 32;
    const int tx = threadIdx.x, ty = threadIdx.y;  // (32, 8)
    bf16* YH = yh + (size_t)b * N_ * D_;
    bf16* YL = yl + (size_t)b * N_ * D_;
#pragma unroll
    for (int i = 0; i < 4; i++) {
        const int r = ty + i * 8;
        const float v = Y[(size_t)(n0 + r) * D_ + d0 + tx];
        t[r][tx] = v;
        bf16 h = __float2bfloat16_rn(v);
        YH[(size_t)(n0 + r) * D_ + d0 + tx] = h;
        YL[(size_t)(n0 + r) * D_ + d0 + tx] = __float2bfloat16_rn(v - __bfloat162float(h));
    }
    __syncthreads();
    bf16* TH = th + (size_t)b * D_ * N_;
    bf16* TL = tl + (size_t)b * D_ * N_;
#pragma unroll
    for (int i = 0; i < 4; i++) {
        int r = ty + i * 8;
        float v = t[tx][r];
        bf16 h = __float2bfloat16_rn(v);
        TH[(size_t)(d0 + r) * N_ + n0 + tx] = h;
        TL[(size_t)(d0 + r) * N_ + n0 + tx] = __float2bfloat16_rn(v - __bfloat162float(h));
    }
}

// ---------------- reductions ----------------
__device__ __forceinline__ float warpMax(float v) {
#pragma unroll
    for (int o = 16; o; o >>= 1) v = fmaxf(v, __shfl_xor_sync(0xffffffffu, v, o));
    return v;
}
__device__ __forceinline__ float warpSum(float v) {
#pragma unroll
    for (int o = 16; o; o >>= 1) v += __shfl_xor_sync(0xffffffffu, v, o);
    return v;
}

// ---------------- positional softmax (R11 proven version) ----------------
__global__ void __launch_bounds__(256) pos_kernel(
    const float* __restrict__ coords, const float* __restrict__ pe, float* __restrict__ Q)
{
    __shared__ float pesh[6];
    __shared__ float red[8], red2[8];
    const int p = blockIdx.x;
    const int tid = threadIdx.x;
    if (tid < 6) pesh[tid] = pe[p * 6 + tid];
    __syncthreads();

    const float* cbase = coords + (size_t)p * N_ * 6;
    float z[4];
#pragma unroll
    for (int i = 0; i < 4; i++) {
        const float* c = cbase + (size_t)(i * 256 + tid) * 6;
        float2 c01 = *(const float2*)(c);
        float2 c23 = *(const float2*)(c + 2);
        float2 c45 = *(const float2*)(c + 4);
        z[i] = c01.x * pesh[0] + c01.y * pesh[1] + c23.x * pesh[2]
             + c23.y * pesh[3] + c45.x * pesh[4] + c45.y * pesh[5];
    }
    float m = fmaxf(fmaxf(z[0], z[1]), fmaxf(z[2], z[3]));
    m = warpMax(m);
    if ((tid & 31) == 0) red[tid >> 5] = m;
    __syncthreads();
    m = red[0];
#pragma unroll
    for (int i = 1; i < 8; i++) m = fmaxf(m, red[i]);

    float e[4], s = 0.f;
#pragma unroll
    for (int i = 0; i < 4; i++) { e[i] = __expf(z[i] - m); s += e[i]; }
    s = warpSum(s);
    if ((tid & 31) == 0) red2[tid >> 5] = s;
    __syncthreads();
    s = red2[0];
#pragma unroll
    for (int i = 1; i < 8; i++) s += red2[i];
    const float inv = 1.f / s;
#pragma unroll
    for (int i = 0; i < 4; i++)
        Q[(size_t)p * N_ + i * 256 + tid] = e[i] * inv;
}

// -------- row softmax + gate mix + entropy (R11 proven linear-row mapping) --------
__global__ void __launch_bounds__(256) mix_kernel(
    const float* __restrict__ S, const float* __restrict__ Q,
    const float* __restrict__ gating, const float* __restrict__ temp,
    bf16* __restrict__ AH, bf16* __restrict__ AL, float* __restrict__ hmap)
{
    const int row  = blockIdx.x * 8 + (threadIdx.x >> 5);   // b*N + n
    const int lane = threadIdx.x & 31;

    // hoist scalar loads so sigmoid chain overlaps the S long-scoreboard reads
    const float gv = gating[0], tv = temp[0];

    const float4* s4 = (const float4*)(S + (size_t)row * N_);
    const float4* q4 = (const float4*)(Q + (size_t)(row & (N_ - 1)) * N_);

    float4 v[8];
#pragma unroll
    for (int i = 0; i < 8; i++) v[i] = s4[lane + 32 * i];

    const float gt = 1.f / (1.f + __expf(-gv));
    const float og = 1.f - gt;

    float m = -1e30f;
#pragma unroll
    for (int i = 0; i < 8; i++)
        m = fmaxf(m, fmaxf(fmaxf(v[i].x, v[i].y), fmaxf(v[i].z, v[i].w)));
    m = warpMax(m);

    float ssum = 0.f;
#pragma unroll
    for (int i = 0; i < 8; i++) {
        v[i].x = __expf(v[i].x - m); v[i].y = __expf(v[i].y - m);
        v[i].z = __expf(v[i].z - m); v[i].w = __expf(v[i].w - m);
        ssum += v[i].x + v[i].y + v[i].z + v[i].w;
    }
    ssum = warpSum(ssum);
    const float inv = 1.f / ssum;

    uint2* AH2 = (uint2*)(AH + (size_t)row * N_);
    uint2* AL2 = (uint2*)(AL + (size_t)row * N_);
    float H = 0.f;
#pragma unroll
    for (int i = 0; i < 8; i++) {
        float4 qv = q4[lane + 32 * i];
        float a[4];
        a[0] = og * v[i].x * inv + gt * qv.x;
        a[1] = og * v[i].y * inv + gt * qv.y;
        a[2] = og * v[i].z * inv + gt * qv.z;
        a[3] = og * v[i].w * inv + gt * qv.w;
        H -= a[0] * __logf(a[0] + 1e-8f) + a[1] * __logf(a[1] + 1e-8f)
           + a[2] * __logf(a[2] + 1e-8f) + a[3] * __logf(a[3] + 1e-8f);
        bf16 h[4], l[4];
#pragma unroll
        for (int j = 0; j < 4; j++) {
            h[j] = __float2bfloat16_rn(a[j]);
            l[j] = __float2bfloat16_rn(a[j] - __bfloat162float(h[j]));
        }
        AH2[lane + 32 * i] = *(uint2*)h;
        AL2[lane + 32 * i] = *(uint2*)l;
    }
    H = warpSum(H);
    if (lane == 0) {
        const float sig = 1.f / (1.f + __expf(-tv * H));
        hmap[row] = 2.f * (1.f - sig);
    }
}

// ---------------- launch ----------------
extern "C" void kernel_launch(void* const* d_in, const int* in_sizes, int n_in,
                              void* d_out, int out_size)
{
    const float* x      = (const float*)d_in[0];
    const float* y      = (const float*)d_in[1];
    const float* coords = (const float*)d_in[2];
    const float* W      = (const float*)d_in[3];
    const float* pe     = (const float*)d_in[4];
    const float* gating = (const float*)d_in[5];
    const float* temp   = (const float*)d_in[6];

    float* out  = (float*)d_out;                // [B,N,D]
    float* hmap = out + (size_t)B_ * N_ * D_;   // [B,N,1]

    float *Sb, *Qb;
    bf16 *xh, *yh, *yl, *wh, *wl, *kh, *kl, *yth, *ytl, *ah, *al;
    cudaGetSymbolAddress((void**)&Sb, g_S);
    cudaGetSymbolAddress((void**)&Qb, g_Q);
    cudaGetSymbolAddress((void**)&xh, g_xh);
    cudaGetSymbolAddress((void**)&yh, g_yh);  cudaGetSymbolAddress((void**)&yl, g_yl);
    cudaGetSymbolAddress((void**)&wh, g_wh);  cudaGetSymbolAddress((void**)&wl, g_wl);
    cudaGetSymbolAddress((void**)&kh, g_kh);  cudaGetSymbolAddress((void**)&kl, g_kl);
    cudaGetSymbolAddress((void**)&yth, g_yth); cudaGetSymbolAddress((void**)&ytl, g_ytl);
    cudaGetSymbolAddress((void**)&ah, g_ah);  cudaGetSymbolAddress((void**)&al, g_al);

    cudaFuncSetAttribute((const void*)gemm_mma<true, 3>,  cudaFuncAttributeMaxDynamicSharedMemorySize, SMEM_BYTES);
    cudaFuncSetAttribute((const void*)gemm_mma<false, 2>, cudaFuncAttributeMaxDynamicSharedMemorySize, SMEM_BYTES);
    cudaFuncSetAttribute((const void*)gemm_mma<false, 3>, cudaFuncAttributeMaxDynamicSharedMemorySize, SMEM_BYTES);

    const int nBND4 = (B_ * N_ * D_) / 4;
    const int nDD4  = (D_ * D_) / 4;

    split_Ty<<<dim3(N_ / 32, D_ / 32, B_), dim3(32, 8)>>>(y, yh, yl, yth, ytl);
    split_h<<<(nBND4 + 255) / 256, 256>>>((const float4*)x, (uint2*)xh, nBND4);
    split_k<<<(nDD4  + 255) / 256, 256>>>((const float4*)W, (uint2*)wh, (uint2*)wl, nDD4);

    pos_kernel<<<N_, 256>>>(coords, pe, Qb);

    // 1) k = y @ W^T  (M=16384, N=768, K=768) -> kh/kl bf16 directly (3-term)
    gemm_mma<true, 3><<<dim3(D_ / 128, (B_ * N_) / 128, 1), 128, SMEM_BYTES>>>(
        yh, yl, wh, wl, nullptr, kh, kl, D_, D_, D_, D_, 0, 0, 0, 1.0f);

    // 2) S = (x @ k^T) * SCALE, batched over B -> fp32 (2-term)
    gemm_mma<false, 2><<<dim3(N_ / 128, N_ / 128, B_), 128, SMEM_BYTES>>>(
        xh, xh, kh, kl, Sb, nullptr, nullptr, D_, D_, D_, N_,
        (size_t)N_ * D_, (size_t)N_ * D_, (size_t)N_ * N_, SCALE_);

    // 3) softmax + mix + entropy -> attn bf16 hi/lo + hmap (warp per row)
    mix_kernel<<<(B_ * N_) / 8, 256>>>(Sb, Qb, gating, temp, ah, al, hmap);

    // 4) out = attn @ y (B operand = y^T per batch, K=1024) (3-term)
    gemm_mma<false, 3><<<dim3(D_ / 128, N_ / 128, B_), 128, SMEM_BYTES>>>(
        ah, al, yth, ytl, out, nullptr, nullptr, N_, N_, N_, D_,
        (size_t)N_ * N_, (size_t)D_ * N_, (size_t)N_ * D_, 1.0f);
}

// round 14
// speedup vs baseline: 1.4981x; 1.0068x over previous
#include <cuda_runtime.h>
#include <cuda_bf16.h>
#include <cstdint>

#define B_ 16
#define N_ 1024
#define D_ 768

typedef __nv_bfloat16 bf16;

static const float SCALE_ = 0.03608439182435161f; // 768^-0.5

// ---------------- scratch (device globals: allocation-free contract) ----------------
__device__ __align__(16) float g_S[(size_t)B_ * N_ * N_];   // 64 MB fp32 scores
__device__ __align__(16) float g_Q[(size_t)N_ * N_];        // 4 MB  pos softmax
__device__ __align__(16) bf16 g_xh[(size_t)B_ * N_ * D_];
__device__ __align__(16) bf16 g_yh[(size_t)B_ * N_ * D_], g_yl[(size_t)B_ * N_ * D_];
__device__ __align__(16) bf16 g_wh[(size_t)D_ * D_],      g_wl[(size_t)D_ * D_];
__device__ __align__(16) bf16 g_kh[(size_t)B_ * N_ * D_], g_kl[(size_t)B_ * N_ * D_];
__device__ __align__(16) bf16 g_yth[(size_t)B_ * D_ * N_], g_ytl[(size_t)B_ * D_ * N_];
__device__ __align__(16) bf16 g_ah[(size_t)B_ * N_ * N_],  g_al[(size_t)B_ * N_ * N_];

// ---------------- helpers ----------------
__device__ __forceinline__ uint32_t smem_u32(const void* p) {
    uint32_t a;
    asm("{ .reg .u64 t; cvta.to.shared.u64 t, %1; cvt.u32.u64 %0, t; }" : "=r"(a) : "l"(p));
    return a;
}
#define CP_COMMIT() asm volatile("cp.async.commit_group;" ::: "memory")

__device__ __forceinline__ void mma16816(float* c, const uint32_t* a, const uint32_t* b) {
    asm volatile(
        "mma.sync.aligned.m16n8k16.row.col.f32.bf16.bf16.f32 "
        "{%0,%1,%2,%3}, {%4,%5,%6,%7}, {%8,%9}, {%0,%1,%2,%3};"
        : "+f"(c[0]), "+f"(c[1]), "+f"(c[2]), "+f"(c[3])
        : "r"(a[0]), "r"(a[1]), "r"(a[2]), "r"(a[3]), "r"(b[0]), "r"(b[1]));
}
__device__ __forceinline__ void ldsm4(uint32_t* r, uint32_t addr) {
    asm volatile("ldmatrix.sync.aligned.m8n8.x4.shared.b16 {%0,%1,%2,%3}, [%4];"
        : "=r"(r[0]), "=r"(r[1]), "=r"(r[2]), "=r"(r[3]) : "r"(addr));
}

// ---------------- HMMA split-bf16 GEMM (FROZEN since R10) ----------------
#define TILE_SZ 8192          // 128 * 64
#define SMEM_BYTES 98304      // 96 KB (both variants)

__device__ __forceinline__ void fill_tile(uint32_t dst, const bf16* __restrict__ g,
                                          int ld, int r0, int k0, int tid) {
#pragma unroll
    for (int it = 0; it < 4; it++) {
        int idx = it * 128 + tid;
        int r = idx >> 2, b = idx & 3;
        uint32_t sw = (uint32_t)(r * 64 + ((b ^ ((r >> 1) & 3)) * 16));
        const bf16* src = g + (size_t)(r0 + r) * ld + k0 + b * 8;
        asm volatile("cp.async.cg.shared.global [%0], [%1], 16;"
                     :: "r"(dst + sw), "l"(src));
    }
}

template <int TERMS>
__device__ __forceinline__ void fill_chunk(uint32_t S0,
                                           const bf16* Ah_, const bf16* Al_,
                                           const bf16* Bh_, const bf16* Bl_,
                                           int lda, int ldb, int m0, int n0, int k0, int tid) {
    constexpr int BH = (TERMS == 3) ? 2 : 1;
    fill_tile(S0 + 0 * TILE_SZ, Ah_, lda, m0, k0, tid);
    if (TERMS == 3) fill_tile(S0 + 1 * TILE_SZ, Al_, lda, m0, k0, tid);
    fill_tile(S0 + BH * TILE_SZ,       Bh_, ldb, n0, k0, tid);
    fill_tile(S0 + (BH + 1) * TILE_SZ, Bl_, ldb, n0, k0, tid);
}

template <bool SPLIT_OUT, int TERMS>
__global__ void __launch_bounds__(128, 2) gemm_mma(
    const bf16* __restrict__ Ah_, const bf16* __restrict__ Al_,
    const bf16* __restrict__ Bh_, const bf16* __restrict__ Bl_,
    float* __restrict__ C, bf16* __restrict__ Ch, bf16* __restrict__ Cl,
    int K, int lda, int ldb, int ldc,
    size_t sA, size_t sB, size_t sC, float alpha)
{
    constexpr int NST = (TERMS == 3) ? 3 : 4;
    constexpr int STG = ((TERMS == 3) ? 4 : 3) * TILE_SZ;
    constexpr int BH  = (TERMS == 3) ? 2 : 1;

    extern __shared__ char sm[];
    const uint32_t sb = smem_u32(sm);
    const int tid = threadIdx.x, lane = tid & 31, w = tid >> 5;
    const int wm = w & 1, wn = w >> 1;
    const int g = lane >> 2, tig = lane & 3;
    const int m0 = blockIdx.y * 128, n0 = blockIdx.x * 128;

    Ah_ += (size_t)blockIdx.z * sA; Al_ += (size_t)blockIdx.z * sA;
    Bh_ += (size_t)blockIdx.z * sB; Bl_ += (size_t)blockIdx.z * sB;

    const int rowA = wm * 64 + (lane & 7) + (lane & 8);
    const int hA = (lane >> 4) & 1;
    const int xA = (rowA >> 1) & 3;
    const uint32_t aRow = (uint32_t)(rowA * 64);
    const uint32_t aBlk0 = (uint32_t)(((0 + hA) ^ xA) * 16);
    const uint32_t aBlk1 = (uint32_t)(((2 + hA) ^ xA) * 16);
    const int rowB = wn * 64 + (lane & 7) + ((lane & 16) >> 1);
    const int hB = (lane >> 3) & 1;
    const int xB = (rowB >> 1) & 3;
    const uint32_t bRow = (uint32_t)(rowB * 64);
    const uint32_t bBlk0 = (uint32_t)(((0 + hB) ^ xB) * 16);
    const uint32_t bBlk1 = (uint32_t)(((2 + hB) ^ xB) * 16);

    float acc[4][8][4];
#pragma unroll
    for (int i = 0; i < 4; i++)
#pragma unroll
        for (int j = 0; j < 8; j++)
#pragma unroll
            for (int c = 0; c < 4; c++) acc[i][j][c] = 0.f;

    const int KT = K >> 5;

#pragma unroll
    for (int p = 0; p < NST; p++) {
        fill_chunk<TERMS>(sb + p * STG, Ah_, Al_, Bh_, Bl_, lda, ldb, m0, n0, p * 32, tid);
        CP_COMMIT();
    }

    for (int kt = 0; kt < KT; ++kt) {
        asm volatile("cp.async.wait_group %0;" :: "n"(NST - 2) : "memory");
        __syncthreads();
        const uint32_t S0 = sb + (kt % NST) * STG;
        const uint32_t pAh = S0, pAl = S0 + TILE_SZ;
        const uint32_t pBh = S0 + BH * TILE_SZ, pBl = S0 + (BH + 1) * TILE_SZ;

        uint32_t ah[4][4], al[4][4], bh[8][2], bl[8][2];
#pragma unroll
        for (int mf = 0; mf < 4; mf++) {
            ldsm4(&ah[mf][0], pAh + aRow + mf * 1024 + aBlk0);
            if (TERMS == 3) ldsm4(&al[mf][0], pAl + aRow + mf * 1024 + aBlk0);
        }
#pragma unroll
        for (int p = 0; p < 4; p++) {
            ldsm4(&bh[2 * p][0], pBh + bRow + p * 1024 + bBlk0);
            ldsm4(&bl[2 * p][0], pBl + bRow + p * 1024 + bBlk0);
        }
        if (kt >= 1) {
            if (kt + NST - 1 < KT)
                fill_chunk<TERMS>(sb + ((kt + NST - 1) % NST) * STG,
                                  Ah_, Al_, Bh_, Bl_, lda, ldb, m0, n0,
                                  (kt + NST - 1) * 32, tid);
            CP_COMMIT();
        }
#pragma unroll
        for (int mf = 0; mf < 4; mf++)
#pragma unroll
            for (int nf = 0; nf < 8; nf++)
                mma16816(acc[mf][nf], ah[mf], bh[nf]);
#pragma unroll
        for (int mf = 0; mf < 4; mf++)
#pragma unroll
            for (int nf = 0; nf < 8; nf++)
                mma16816(acc[mf][nf], ah[mf], bl[nf]);
        if (TERMS == 3) {
#pragma unroll
            for (int mf = 0; mf < 4; mf++)
#pragma unroll
                for (int nf = 0; nf < 8; nf++)
                    mma16816(acc[mf][nf], al[mf], bh[nf]);
        }

#pragma unroll
        for (int mf = 0; mf < 4; mf++) {
            ldsm4(&ah[mf][0], pAh + aRow + mf * 1024 + aBlk1);
            if (TERMS == 3) ldsm4(&al[mf][0], pAl + aRow + mf * 1024 + aBlk1);
        }
#pragma unroll
        for (int p = 0; p < 4; p++) {
            ldsm4(&bh[2 * p][0], pBh + bRow + p * 1024 + bBlk1);
            ldsm4(&bl[2 * p][0], pBl + bRow + p * 1024 + bBlk1);
        }
#pragma unroll
        for (int mf = 0; mf < 4; mf++)
#pragma unroll
            for (int nf = 0; nf < 8; nf++)
                mma16816(acc[mf][nf], ah[mf], bh[nf]);
#pragma unroll
        for (int mf = 0; mf < 4; mf++)
#pragma unroll
            for (int nf = 0; nf < 8; nf++)
                mma16816(acc[mf][nf], ah[mf], bl[nf]);
        if (TERMS == 3) {
#pragma unroll
            for (int mf = 0; mf < 4; mf++)
#pragma unroll
                for (int nf = 0; nf < 8; nf++)
                    mma16816(acc[mf][nf], al[mf], bh[nf]);
        }
    }

    // epilogue
#pragma unroll
    for (int mf = 0; mf < 4; mf++) {
#pragma unroll
        for (int nf = 0; nf < 8; nf++) {
            const int row = m0 + wm * 64 + mf * 16 + g;
            const int col = n0 + wn * 64 + nf * 8 + tig * 2;
            float c0 = acc[mf][nf][0] * alpha, c1 = acc[mf][nf][1] * alpha;
            float c2 = acc[mf][nf][2] * alpha, c3 = acc[mf][nf][3] * alpha;
            if (SPLIT_OUT) {
                bf16 h0 = __float2bfloat16_rn(c0), h1 = __float2bfloat16_rn(c1);
                bf16 h2 = __float2bfloat16_rn(c2), h3 = __float2bfloat16_rn(c3);
                bf16 l0 = __float2bfloat16_rn(c0 - __bfloat162float(h0));
                bf16 l1 = __float2bfloat16_rn(c1 - __bfloat162float(h1));
                bf16 l2 = __float2bfloat16_rn(c2 - __bfloat162float(h2));
                bf16 l3 = __float2bfloat16_rn(c3 - __bfloat162float(h3));
                bf16 ph0[2] = {h0, h1}, ph2[2] = {h2, h3};
                bf16 pl0[2] = {l0, l1}, pl2[2] = {l2, l3};
                *(uint32_t*)&Ch[(size_t)row * ldc + col]       = *(uint32_t*)ph0;
                *(uint32_t*)&Ch[(size_t)(row + 8) * ldc + col] = *(uint32_t*)ph2;
                *(uint32_t*)&Cl[(size_t)row * ldc + col]       = *(uint32_t*)pl0;
                *(uint32_t*)&Cl[(size_t)(row + 8) * ldc + col] = *(uint32_t*)pl2;
            } else {
                float* Cp = C + (size_t)blockIdx.z * sC;
                float2 v0 = {c0, c1}, v2 = {c2, c3};
                *(float2*)&Cp[(size_t)row * ldc + col]       = v0;
                *(float2*)&Cp[(size_t)(row + 8) * ldc + col] = v2;
            }
        }
    }
}

// ---------------- fp32 -> (hi,lo) bf16 split ----------------
__global__ void __launch_bounds__(256) split_k(const float4* __restrict__ in,
                                               uint2* __restrict__ hi, uint2* __restrict__ lo,
                                               int n4) {
    int i = blockIdx.x * 256 + threadIdx.x;
    if (i >= n4) return;
    float4 v = in[i];
    float xs[4] = {v.x, v.y, v.z, v.w};
    bf16 h[4], l[4];
#pragma unroll
    for (int j = 0; j < 4; j++) {
        h[j] = __float2bfloat16_rn(xs[j]);
        l[j] = __float2bfloat16_rn(xs[j] - __bfloat162float(h[j]));
    }
    hi[i] = *(uint2*)h;
    lo[i] = *(uint2*)l;
}

// ---------------- fp32 -> hi bf16 only ----------------
__global__ void __launch_bounds__(256) split_h(const float4* __restrict__ in,
                                               uint2* __restrict__ hi, int n4) {
    int i = blockIdx.x * 256 + threadIdx.x;
    if (i >= n4) return;
    float4 v = in[i];
    float xs[4] = {v.x, v.y, v.z, v.w};
    bf16 h[4];
#pragma unroll
    for (int j = 0; j < 4; j++) h[j] = __float2bfloat16_rn(xs[j]);
    hi[i] = *(uint2*)h;
}

// ------- y [B,N,D]: split to yh/yl AND transposed yth/ytl [B,D,N] in one pass -------
__global__ void __launch_bounds__(256) split_Ty(const float* __restrict__ y,
                                                bf16* __restrict__ yh, bf16* __restrict__ yl,
                                                bf16* __restrict__ th, bf16* __restrict__ tl) {
    __shared__ float t[32][33];
    const int b = blockIdx.z;
    const float* Y = y + (size_t)b * N_ * D_;
    const int n0 = blockIdx.x * 32, d0 = blockIdx.y * 32;
    const int tx = threadIdx.x, ty = threadIdx.y;  // (32, 8)
    bf16* YH = yh + (size_t)b * N_ * D_;
    bf16* YL = yl + (size_t)b * N_ * D_;
#pragma unroll
    for (int i = 0; i < 4; i++) {
        const int r = ty + i * 8;
        const float v = Y[(size_t)(n0 + r) * D_ + d0 + tx];
        t[r][tx] = v;
        bf16 h = __float2bfloat16_rn(v);
        YH[(size_t)(n0 + r) * D_ + d0 + tx] = h;
        YL[(size_t)(n0 + r) * D_ + d0 + tx] = __float2bfloat16_rn(v - __bfloat162float(h));
    }
    __syncthreads();
    bf16* TH = th + (size_t)b * D_ * N_;
    bf16* TL = tl + (size_t)b * D_ * N_;
#pragma unroll
    for (int i = 0; i < 4; i++) {
        int r = ty + i * 8;
        float v = t[tx][r];
        bf16 h = __float2bfloat16_rn(v);
        TH[(size_t)(d0 + r) * N_ + n0 + tx] = h;
        TL[(size_t)(d0 + r) * N_ + n0 + tx] = __float2bfloat16_rn(v - __bfloat162float(h));
    }
}

// ---------------- reductions ----------------
__device__ __forceinline__ float warpMax(float v) {
#pragma unroll
    for (int o = 16; o; o >>= 1) v = fmaxf(v, __shfl_xor_sync(0xffffffffu, v, o));
    return v;
}
__device__ __forceinline__ float warpSum(float v) {
#pragma unroll
    for (int o = 16; o; o >>= 1) v += __shfl_xor_sync(0xffffffffu, v, o);
    return v;
}

// ---------------- positional softmax ----------------
__global__ void __launch_bounds__(256) pos_kernel(
    const float* __restrict__ coords, const float* __restrict__ pe, float* __restrict__ Q)
{
    __shared__ float pesh[6];
    __shared__ float red[8], red2[8];
    const int p = blockIdx.x;
    const int tid = threadIdx.x;
    if (tid < 6) pesh[tid] = pe[p * 6 + tid];
    __syncthreads();

    const float* cbase = coords + (size_t)p * N_ * 6;
    float z[4];
#pragma unroll
    for (int i = 0; i < 4; i++) {
        const float* c = cbase + (size_t)(i * 256 + tid) * 6;
        float2 c01 = *(const float2*)(c);
        float2 c23 = *(const float2*)(c + 2);
        float2 c45 = *(const float2*)(c + 4);
        z[i] = c01.x * pesh[0] + c01.y * pesh[1] + c23.x * pesh[2]
             + c23.y * pesh[3] + c45.x * pesh[4] + c45.y * pesh[5];
    }
    float m = fmaxf(fmaxf(z[0], z[1]), fmaxf(z[2], z[3]));
    m = warpMax(m);
    if ((tid & 31) == 0) red[tid >> 5] = m;
    __syncthreads();
    m = red[0];
#pragma unroll
    for (int i = 1; i < 8; i++) m = fmaxf(m, red[i]);

    float e[4], s = 0.f;
#pragma unroll
    for (int i = 0; i < 4; i++) { e[i] = __expf(z[i] - m); s += e[i]; }
    s = warpSum(s);
    if ((tid & 31) == 0) red2[tid >> 5] = s;
    __syncthreads();
    s = red2[0];
#pragma unroll
    for (int i = 1; i < 8; i++) s += red2[i];
    const float inv = 1.f / s;
#pragma unroll
    for (int i = 0; i < 4; i++)
        Q[(size_t)p * N_ + i * 256 + tid] = e[i] * inv;
}

// -------- row softmax + gate mix + entropy; warp per row; attn -> bf16 hi/lo --------
__global__ void __launch_bounds__(256) mix_kernel(
    const float* __restrict__ S, const float* __restrict__ Q,
    const float* __restrict__ gating, const float* __restrict__ temp,
    bf16* __restrict__ AH, bf16* __restrict__ AL, float* __restrict__ hmap)
{
    const int row  = blockIdx.x * 8 + (threadIdx.x >> 5);   // b*N + n
    const int lane = threadIdx.x & 31;
    const float4* s4 = (const float4*)(S + (size_t)row * N_);
    const float4* q4 = (const float4*)(Q + (size_t)(row & (N_ - 1)) * N_);

    float4 v[8];
#pragma unroll
    for (int i = 0; i < 8; i++) v[i] = s4[lane + 32 * i];

    float m = -1e30f;
#pragma unroll
    for (int i = 0; i < 8; i++)
        m = fmaxf(m, fmaxf(fmaxf(v[i].x, v[i].y), fmaxf(v[i].z, v[i].w)));
    m = warpMax(m);

    float ssum = 0.f;
#pragma unroll
    for (int i = 0; i < 8; i++) {
        v[i].x = __expf(v[i].x - m); v[i].y = __expf(v[i].y - m);
        v[i].z = __expf(v[i].z - m); v[i].w = __expf(v[i].w - m);
        ssum += v[i].x + v[i].y + v[i].z + v[i].w;
    }
    ssum = warpSum(ssum);
    const float inv = 1.f / ssum;

    const float gt = 1.f / (1.f + __expf(-gating[0]));
    const float og = 1.f - gt;

    uint2* AH2 = (uint2*)(AH + (size_t)row * N_);
    uint2* AL2 = (uint2*)(AL + (size_t)row * N_);
    float H = 0.f;
#pragma unroll
    for (int i = 0; i < 8; i++) {
        float4 qv = q4[lane + 32 * i];
        float a[4];
        a[0] = og * v[i].x * inv + gt * qv.x;
        a[1] = og * v[i].y * inv + gt * qv.y;
        a[2] = og * v[i].z * inv + gt * qv.z;
        a[3] = og * v[i].w * inv + gt * qv.w;
        H -= a[0] * __logf(a[0] + 1e-8f) + a[1] * __logf(a[1] + 1e-8f)
           + a[2] * __logf(a[2] + 1e-8f) + a[3] * __logf(a[3] + 1e-8f);
        bf16 h[4], l[4];
#pragma unroll
        for (int j = 0; j < 4; j++) {
            h[j] = __float2bfloat16_rn(a[j]);
            l[j] = __float2bfloat16_rn(a[j] - __bfloat162float(h[j]));
        }
        AH2[lane + 32 * i] = *(uint2*)h;
        AL2[lane + 32 * i] = *(uint2*)l;
    }
    H = warpSum(H);
    if (lane == 0) {
        const float sig = 1.f / (1.f + __expf(-temp[0] * H));
        hmap[row] = 2.f * (1.f - sig);
    }
}

// ---------------- launch ----------------
extern "C" void kernel_launch(void* const* d_in, const int* in_sizes, int n_in,
                              void* d_out, int out_size)
{
    const float* x      = (const float*)d_in[0];
    const float* y      = (const float*)d_in[1];
    const float* coords = (const float*)d_in[2];
    const float* W      = (const float*)d_in[3];
    const float* pe     = (const float*)d_in[4];
    const float* gating = (const float*)d_in[5];
    const float* temp   = (const float*)d_in[6];

    float* out  = (float*)d_out;                // [B,N,D]
    float* hmap = out + (size_t)B_ * N_ * D_;   // [B,N,1]

    float *Sb, *Qb;
    bf16 *xh, *yh, *yl, *wh, *wl, *kh, *kl, *yth, *ytl, *ah, *al;
    cudaGetSymbolAddress((void**)&Sb, g_S);
    cudaGetSymbolAddress((void**)&Qb, g_Q);
    cudaGetSymbolAddress((void**)&xh, g_xh);
    cudaGetSymbolAddress((void**)&yh, g_yh);  cudaGetSymbolAddress((void**)&yl, g_yl);
    cudaGetSymbolAddress((void**)&wh, g_wh);  cudaGetSymbolAddress((void**)&wl, g_wl);
    cudaGetSymbolAddress((void**)&kh, g_kh);  cudaGetSymbolAddress((void**)&kl, g_kl);
    cudaGetSymbolAddress((void**)&yth, g_yth); cudaGetSymbolAddress((void**)&ytl, g_ytl);
    cudaGetSymbolAddress((void**)&ah, g_ah);  cudaGetSymbolAddress((void**)&al, g_al);

    cudaFuncSetAttribute((const void*)gemm_mma<true, 3>,  cudaFuncAttributeMaxDynamicSharedMemorySize, SMEM_BYTES);
    cudaFuncSetAttribute((const void*)gemm_mma<false, 2>, cudaFuncAttributeMaxDynamicSharedMemorySize, SMEM_BYTES);
    cudaFuncSetAttribute((const void*)gemm_mma<false, 3>, cudaFuncAttributeMaxDynamicSharedMemorySize, SMEM_BYTES);

    const int nBND4 = (B_ * N_ * D_) / 4;
    const int nDD4  = (D_ * D_) / 4;

    split_Ty<<<dim3(N_ / 32, D_ / 32, B_), dim3(32, 8)>>>(y, yh, yl, yth, ytl);
    split_h<<<(nBND4 + 255) / 256, 256>>>((const float4*)x, (uint2*)xh, nBND4);
    split_k<<<(nDD4  + 255) / 256, 256>>>((const float4*)W, (uint2*)wh, (uint2*)wl, nDD4);

    pos_kernel<<<N_, 256>>>(coords, pe, Qb);

    // 1) k = y @ W^T  (M=16384, N=768, K=768) -> kh/kl bf16 directly (3-term)
    gemm_mma<true, 3><<<dim3(D_ / 128, (B_ * N_) / 128, 1), 128, SMEM_BYTES>>>(
        yh, yl, wh, wl, nullptr, kh, kl, D_, D_, D_, D_, 0, 0, 0, 1.0f);

    // 2) S = (x @ k^T) * SCALE, batched over B -> fp32 (2-term)
    gemm_mma<false, 2><<<dim3(N_ / 128, N_ / 128, B_), 128, SMEM_BYTES>>>(
        xh, xh, kh, kl, Sb, nullptr, nullptr, D_, D_, D_, N_,
        (size_t)N_ * D_, (size_t)N_ * D_, (size_t)N_ * N_, SCALE_);

    // 3) softmax + mix + entropy -> attn bf16 hi/lo + hmap (warp per row)
    mix_kernel<<<(B_ * N_) / 8, 256>>>(Sb, Qb, gating, temp, ah, al, hmap);

    // 4) out = attn @ y (B operand = y^T per batch, K=1024) (3-term)
    gemm_mma<false, 3><<<dim3(D_ / 128, N_ / 128, B_), 128, SMEM_BYTES>>>(
        ah, al, yth, ytl, out, nullptr, nullptr, N_, N_, N_, D_,
        (size_t)N_ * N_, (size_t)D_ * N_, (size_t)N_ * D_, 1.0f);
}

// round 15
// speedup vs baseline: 1.5344x; 1.0242x over previous
#include <cuda_runtime.h>
#include <cuda_bf16.h>
#include <cstdint>

#define B_ 16
#define N_ 1024
#define D_ 768

typedef __nv_bfloat16 bf16;

static const float SCALE_ = 0.03608439182435161f; // 768^-0.5

// ---------------- scratch (device globals: allocation-free contract) ----------------
__device__ __align__(16) float g_S[(size_t)B_ * N_ * N_];   // 64 MB fp32 scores
__device__ __align__(16) float g_Q[(size_t)N_ * N_];        // 4 MB  pos softmax
__device__ __align__(16) bf16 g_xh[(size_t)B_ * N_ * D_];
__device__ __align__(16) bf16 g_yh[(size_t)B_ * N_ * D_], g_yl[(size_t)B_ * N_ * D_];
__device__ __align__(16) bf16 g_wh[(size_t)D_ * D_],      g_wl[(size_t)D_ * D_];
__device__ __align__(16) bf16 g_kh[(size_t)B_ * N_ * D_], g_kl[(size_t)B_ * N_ * D_];
__device__ __align__(16) bf16 g_yth[(size_t)B_ * D_ * N_], g_ytl[(size_t)B_ * D_ * N_];
__device__ __align__(16) bf16 g_ah[(size_t)B_ * N_ * N_],  g_al[(size_t)B_ * N_ * N_];

// ---------------- helpers ----------------
__device__ __forceinline__ uint32_t smem_u32(const void* p) {
    uint32_t a;
    asm("{ .reg .u64 t; cvta.to.shared.u64 t, %1; cvt.u32.u64 %0, t; }" : "=r"(a) : "l"(p));
    return a;
}
#define CP_COMMIT() asm volatile("cp.async.commit_group;" ::: "memory")

__device__ __forceinline__ void mma16816(float* c, const uint32_t* a, const uint32_t* b) {
    asm volatile(
        "mma.sync.aligned.m16n8k16.row.col.f32.bf16.bf16.f32 "
        "{%0,%1,%2,%3}, {%4,%5,%6,%7}, {%8,%9}, {%0,%1,%2,%3};"
        : "+f"(c[0]), "+f"(c[1]), "+f"(c[2]), "+f"(c[3])
        : "r"(a[0]), "r"(a[1]), "r"(a[2]), "r"(a[3]), "r"(b[0]), "r"(b[1]));
}
__device__ __forceinline__ void ldsm4(uint32_t* r, uint32_t addr) {
    asm volatile("ldmatrix.sync.aligned.m8n8.x4.shared.b16 {%0,%1,%2,%3}, [%4];"
        : "=r"(r[0]), "=r"(r[1]), "=r"(r[2]), "=r"(r[3]) : "r"(addr));
}
__device__ __forceinline__ uint32_t packhl(float a, float b, uint32_t& lo) {
    bf16 h0 = __float2bfloat16_rn(a), h1 = __float2bfloat16_rn(b);
    bf16 l0 = __float2bfloat16_rn(a - __bfloat162float(h0));
    bf16 l1 = __float2bfloat16_rn(b - __bfloat162float(h1));
    bf16 pl[2] = {l0, l1};
    lo = *(uint32_t*)pl;
    bf16 ph[2] = {h0, h1};
    return *(uint32_t*)ph;
}

// ---------------- HMMA split-bf16 GEMM (mainloop FROZEN since R10) ----------------
#define TILE_SZ 8192          // 128 * 64
#define SMEM_BYTES 98304      // 96 KB (both variants)

__device__ __forceinline__ void fill_tile(uint32_t dst, const bf16* __restrict__ g,
                                          int ld, int r0, int k0, int tid) {
#pragma unroll
    for (int it = 0; it < 4; it++) {
        int idx = it * 128 + tid;
        int r = idx >> 2, b = idx & 3;
        uint32_t sw = (uint32_t)(r * 64 + ((b ^ ((r >> 1) & 3)) * 16));
        const bf16* src = g + (size_t)(r0 + r) * ld + k0 + b * 8;
        asm volatile("cp.async.cg.shared.global [%0], [%1], 16;"
                     :: "r"(dst + sw), "l"(src));
    }
}

template <int TERMS>
__device__ __forceinline__ void fill_chunk(uint32_t S0,
                                           const bf16* Ah_, const bf16* Al_,
                                           const bf16* Bh_, const bf16* Bl_,
                                           int lda, int ldb, int m0, int n0, int k0, int tid) {
    constexpr int BH = (TERMS == 3) ? 2 : 1;
    fill_tile(S0 + 0 * TILE_SZ, Ah_, lda, m0, k0, tid);
    if (TERMS == 3) fill_tile(S0 + 1 * TILE_SZ, Al_, lda, m0, k0, tid);
    fill_tile(S0 + BH * TILE_SZ,       Bh_, ldb, n0, k0, tid);
    fill_tile(S0 + (BH + 1) * TILE_SZ, Bl_, ldb, n0, k0, tid);
}

template <bool SPLIT_OUT, int TERMS>
__global__ void __launch_bounds__(128, 2) gemm_mma(
    const bf16* __restrict__ Ah_, const bf16* __restrict__ Al_,
    const bf16* __restrict__ Bh_, const bf16* __restrict__ Bl_,
    float* __restrict__ C, bf16* __restrict__ Ch, bf16* __restrict__ Cl,
    int K, int lda, int ldb, int ldc,
    size_t sA, size_t sB, size_t sC, float alpha)
{
    constexpr int NST = (TERMS == 3) ? 3 : 4;
    constexpr int STG = ((TERMS == 3) ? 4 : 3) * TILE_SZ;
    constexpr int BH  = (TERMS == 3) ? 2 : 1;

    extern __shared__ char sm[];
    const uint32_t sb = smem_u32(sm);
    const int tid = threadIdx.x, lane = tid & 31, w = tid >> 5;
    const int wm = w & 1, wn = w >> 1;
    const int g = lane >> 2, tig = lane & 3;
    const int m0 = blockIdx.y * 128, n0 = blockIdx.x * 128;

    Ah_ += (size_t)blockIdx.z * sA; Al_ += (size_t)blockIdx.z * sA;
    Bh_ += (size_t)blockIdx.z * sB; Bl_ += (size_t)blockIdx.z * sB;

    const int rowA = wm * 64 + (lane & 7) + (lane & 8);
    const int hA = (lane >> 4) & 1;
    const int xA = (rowA >> 1) & 3;
    const uint32_t aRow = (uint32_t)(rowA * 64);
    const uint32_t aBlk0 = (uint32_t)(((0 + hA) ^ xA) * 16);
    const uint32_t aBlk1 = (uint32_t)(((2 + hA) ^ xA) * 16);
    const int rowB = wn * 64 + (lane & 7) + ((lane & 16) >> 1);
    const int hB = (lane >> 3) & 1;
    const int xB = (rowB >> 1) & 3;
    const uint32_t bRow = (uint32_t)(rowB * 64);
    const uint32_t bBlk0 = (uint32_t)(((0 + hB) ^ xB) * 16);
    const uint32_t bBlk1 = (uint32_t)(((2 + hB) ^ xB) * 16);

    float acc[4][8][4];
#pragma unroll
    for (int i = 0; i < 4; i++)
#pragma unroll
        for (int j = 0; j < 8; j++)
#pragma unroll
            for (int c = 0; c < 4; c++) acc[i][j][c] = 0.f;

    const int KT = K >> 5;

#pragma unroll
    for (int p = 0; p < NST; p++) {
        fill_chunk<TERMS>(sb + p * STG, Ah_, Al_, Bh_, Bl_, lda, ldb, m0, n0, p * 32, tid);
        CP_COMMIT();
    }

    for (int kt = 0; kt < KT; ++kt) {
        asm volatile("cp.async.wait_group %0;" :: "n"(NST - 2) : "memory");
        __syncthreads();
        const uint32_t S0 = sb + (kt % NST) * STG;
        const uint32_t pAh = S0, pAl = S0 + TILE_SZ;
        const uint32_t pBh = S0 + BH * TILE_SZ, pBl = S0 + (BH + 1) * TILE_SZ;

        uint32_t ah[4][4], al[4][4], bh[8][2], bl[8][2];
#pragma unroll
        for (int mf = 0; mf < 4; mf++) {
            ldsm4(&ah[mf][0], pAh + aRow + mf * 1024 + aBlk0);
            if (TERMS == 3) ldsm4(&al[mf][0], pAl + aRow + mf * 1024 + aBlk0);
        }
#pragma unroll
        for (int p = 0; p < 4; p++) {
            ldsm4(&bh[2 * p][0], pBh + bRow + p * 1024 + bBlk0);
            ldsm4(&bl[2 * p][0], pBl + bRow + p * 1024 + bBlk0);
        }
        if (kt >= 1) {
            if (kt + NST - 1 < KT)
                fill_chunk<TERMS>(sb + ((kt + NST - 1) % NST) * STG,
                                  Ah_, Al_, Bh_, Bl_, lda, ldb, m0, n0,
                                  (kt + NST - 1) * 32, tid);
            CP_COMMIT();
        }
#pragma unroll
        for (int mf = 0; mf < 4; mf++)
#pragma unroll
            for (int nf = 0; nf < 8; nf++)
                mma16816(acc[mf][nf], ah[mf], bh[nf]);
#pragma unroll
        for (int mf = 0; mf < 4; mf++)
#pragma unroll
            for (int nf = 0; nf < 8; nf++)
                mma16816(acc[mf][nf], ah[mf], bl[nf]);
        if (TERMS == 3) {
#pragma unroll
            for (int mf = 0; mf < 4; mf++)
#pragma unroll
                for (int nf = 0; nf < 8; nf++)
                    mma16816(acc[mf][nf], al[mf], bh[nf]);
        }

#pragma unroll
        for (int mf = 0; mf < 4; mf++) {
            ldsm4(&ah[mf][0], pAh + aRow + mf * 1024 + aBlk1);
            if (TERMS == 3) ldsm4(&al[mf][0], pAl + aRow + mf * 1024 + aBlk1);
        }
#pragma unroll
        for (int p = 0; p < 4; p++) {
            ldsm4(&bh[2 * p][0], pBh + bRow + p * 1024 + bBlk1);
            ldsm4(&bl[2 * p][0], pBl + bRow + p * 1024 + bBlk1);
        }
#pragma unroll
        for (int mf = 0; mf < 4; mf++)
#pragma unroll
            for (int nf = 0; nf < 8; nf++)
                mma16816(acc[mf][nf], ah[mf], bh[nf]);
#pragma unroll
        for (int mf = 0; mf < 4; mf++)
#pragma unroll
            for (int nf = 0; nf < 8; nf++)
                mma16816(acc[mf][nf], ah[mf], bl[nf]);
        if (TERMS == 3) {
#pragma unroll
            for (int mf = 0; mf < 4; mf++)
#pragma unroll
                for (int nf = 0; nf < 8; nf++)
                    mma16816(acc[mf][nf], al[mf], bh[nf]);
        }
    }

    // ---------------- epilogue ----------------
    if (SPLIT_OUT) {
        // Stage each mf-slice (32 rows x 128 cols, hi+lo) through SMEM; write with
        // coalesced 16B uint4 stores (full 32B sectors vs 2x-amplified scalar path).
        // SMEM rows padded to 272B: STS banks (4g+tig) all distinct per warp.
        const uint32_t hiB = sb, loB = sb + 32 * 272;
#pragma unroll
        for (int mf = 0; mf < 4; mf++) {
            __syncthreads();   // slice buffer free (mainloop done / prev STG done)
            const uint32_t s0 = (uint32_t)((wm * 16 + g) * 272);
            const uint32_t s1 = (uint32_t)((wm * 16 + g + 8) * 272);
#pragma unroll
            for (int nf = 0; nf < 8; nf++) {
                const uint32_t cb = (uint32_t)(wn * 128 + nf * 16 + tig * 4);
                uint32_t lo0, lo1;
                uint32_t hi0 = packhl(acc[mf][nf][0] * alpha, acc[mf][nf][1] * alpha, lo0);
                uint32_t hi1 = packhl(acc[mf][nf][2] * alpha, acc[mf][nf][3] * alpha, lo1);
                *(uint32_t*)(sm + (hiB - sb) + s0 + cb) = hi0;
                *(uint32_t*)(sm + (hiB - sb) + s1 + cb) = hi1;
                *(uint32_t*)(sm + (loB - sb) + s0 + cb) = lo0;
                *(uint32_t*)(sm + (loB - sb) + s1 + cb) = lo1;
            }
            __syncthreads();
            // copy 32 rows x 256B (hi) + same (lo): 1024 chunks of 16B, 128 threads
#pragma unroll
            for (int it = 0; it < 8; it++) {
                const int chunk = it * 128 + tid;
                const int isLo = chunk >> 9;          // chunks 512..1023 -> lo
                const int c2 = chunk & 511;
                const int r = c2 >> 4, cs = c2 & 15;  // r: 0..31, cs: 0..15
                uint4 val = *(const uint4*)(sm + (isLo ? (loB - sb) : 0) + r * 272 + cs * 16);
                const int grow = m0 + (r >> 4) * 64 + mf * 16 + (r & 15);
                bf16* dst = isLo ? Cl : Ch;
                *(uint4*)&dst[(size_t)grow * ldc + n0 + cs * 8] = val;
            }
        }
    } else {
#pragma unroll
        for (int mf = 0; mf < 4; mf++) {
#pragma unroll
            for (int nf = 0; nf < 8; nf++) {
                const int row = m0 + wm * 64 + mf * 16 + g;
                const int col = n0 + wn * 64 + nf * 8 + tig * 2;
                float c0 = acc[mf][nf][0] * alpha, c1 = acc[mf][nf][1] * alpha;
                float c2 = acc[mf][nf][2] * alpha, c3 = acc[mf][nf][3] * alpha;
                float* Cp = C + (size_t)blockIdx.z * sC;
                float2 v0 = {c0, c1}, v2 = {c2, c3};
                *(float2*)&Cp[(size_t)row * ldc + col]       = v0;
                *(float2*)&Cp[(size_t)(row + 8) * ldc + col] = v2;
            }
        }
    }
}

// ---------------- fp32 -> (hi,lo) bf16 split ----------------
__global__ void __launch_bounds__(256) split_k(const float4* __restrict__ in,
                                               uint2* __restrict__ hi, uint2* __restrict__ lo,
                                               int n4) {
    int i = blockIdx.x * 256 + threadIdx.x;
    if (i >= n4) return;
    float4 v = in[i];
    float xs[4] = {v.x, v.y, v.z, v.w};
    bf16 h[4], l[4];
#pragma unroll
    for (int j = 0; j < 4; j++) {
        h[j] = __float2bfloat16_rn(xs[j]);
        l[j] = __float2bfloat16_rn(xs[j] - __bfloat162float(h[j]));
    }
    hi[i] = *(uint2*)h;
    lo[i] = *(uint2*)l;
}

// ---------------- fp32 -> hi bf16 only ----------------
__global__ void __launch_bounds__(256) split_h(const float4* __restrict__ in,
                                               uint2* __restrict__ hi, int n4) {
    int i = blockIdx.x * 256 + threadIdx.x;
    if (i >= n4) return;
    float4 v = in[i];
    float xs[4] = {v.x, v.y, v.z, v.w};
    bf16 h[4];
#pragma unroll
    for (int j = 0; j < 4; j++) h[j] = __float2bfloat16_rn(xs[j]);
    hi[i] = *(uint2*)h;
}

// ------- y [B,N,D]: split to yh/yl AND transposed yth/ytl [B,D,N] in one pass -------
__global__ void __launch_bounds__(256) split_Ty(const float* __restrict__ y,
                                                bf16* __restrict__ yh, bf16* __restrict__ yl,
                                                bf16* __restrict__ th, bf16* __restrict__ tl) {
    __shared__ float t[32][33];
    const int b = blockIdx.z;
    const float* Y = y + (size_t)b * N_ * D_;
    const int n0 = blockIdx.x * 32, d0 = blockIdx.y * 32;
    const int tx = threadIdx.x, ty = threadIdx.y;  // (32, 8)
    bf16* YH = yh + (size_t)b * N_ * D_;
    bf16* YL = yl + (size_t)b * N_ * D_;
#pragma unroll
    for (int i = 0; i < 4; i++) {
        const int r = ty + i * 8;
        const float v = Y[(size_t)(n0 + r) * D_ + d0 + tx];
        t[r][tx] = v;
        bf16 h = __float2bfloat16_rn(v);
        YH[(size_t)(n0 + r) * D_ + d0 + tx] = h;
        YL[(size_t)(n0 + r) * D_ + d0 + tx] = __float2bfloat16_rn(v - __bfloat162float(h));
    }
    __syncthreads();
    bf16* TH = th + (size_t)b * D_ * N_;
    bf16* TL = tl + (size_t)b * D_ * N_;
#pragma unroll
    for (int i = 0; i < 4; i++) {
        int r = ty + i * 8;
        float v = t[tx][r];
        bf16 h = __float2bfloat16_rn(v);
        TH[(size_t)(d0 + r) * N_ + n0 + tx] = h;
        TL[(size_t)(d0 + r) * N_ + n0 + tx] = __float2bfloat16_rn(v - __bfloat162float(h));
    }
}

// ---------------- reductions ----------------
__device__ __forceinline__ float warpMax(float v) {
#pragma unroll
    for (int o = 16; o; o >>= 1) v = fmaxf(v, __shfl_xor_sync(0xffffffffu, v, o));
    return v;
}
__device__ __forceinline__ float warpSum(float v) {
#pragma unroll
    for (int o = 16; o; o >>= 1) v += __shfl_xor_sync(0xffffffffu, v, o);
    return v;
}

// ---------------- positional softmax ----------------
__global__ void __launch_bounds__(256) pos_kernel(
    const float* __restrict__ coords, const float* __restrict__ pe, float* __restrict__ Q)
{
    __shared__ float pesh[6];
    __shared__ float red[8], red2[8];
    const int p = blockIdx.x;
    const int tid = threadIdx.x;
    if (tid < 6) pesh[tid] = pe[p * 6 + tid];
    __syncthreads();

    const float* cbase = coords + (size_t)p * N_ * 6;
    float z[4];
#pragma unroll
    for (int i = 0; i < 4; i++) {
        const float* c = cbase + (size_t)(i * 256 + tid) * 6;
        float2 c01 = *(const float2*)(c);
        float2 c23 = *(const float2*)(c + 2);
        float2 c45 = *(const float2*)(c + 4);
        z[i] = c01.x * pesh[0] + c01.y * pesh[1] + c23.x * pesh[2]
             + c23.y * pesh[3] + c45.x * pesh[4] + c45.y * pesh[5];
    }
    float m = fmaxf(fmaxf(z[0], z[1]), fmaxf(z[2], z[3]));
    m = warpMax(m);
    if ((tid & 31) == 0) red[tid >> 5] = m;
    __syncthreads();
    m = red[0];
#pragma unroll
    for (int i = 1; i < 8; i++) m = fmaxf(m, red[i]);

    float e[4], s = 0.f;
#pragma unroll
    for (int i = 0; i < 4; i++) { e[i] = __expf(z[i] - m); s += e[i]; }
    s = warpSum(s);
    if ((tid & 31) == 0) red2[tid >> 5] = s;
    __syncthreads();
    s = red2[0];
#pragma unroll
    for (int i = 1; i < 8; i++) s += red2[i];
    const float inv = 1.f / s;
#pragma unroll
    for (int i = 0; i < 4; i++)
        Q[(size_t)p * N_ + i * 256 + tid] = e[i] * inv;
}

// -------- row softmax + gate mix + entropy; warp per row; attn -> bf16 hi/lo --------
__global__ void __launch_bounds__(256) mix_kernel(
    const float* __restrict__ S, const float* __restrict__ Q,
    const float* __restrict__ gating, const float* __restrict__ temp,
    bf16* __restrict__ AH, bf16* __restrict__ AL, float* __restrict__ hmap)
{
    const int row  = blockIdx.x * 8 + (threadIdx.x >> 5);   // b*N + n
    const int lane = threadIdx.x & 31;
    const float4* s4 = (const float4*)(S + (size_t)row * N_);
    const float4* q4 = (const float4*)(Q + (size_t)(row & (N_ - 1)) * N_);

    float4 v[8];
#pragma unroll
    for (int i = 0; i < 8; i++) v[i] = s4[lane + 32 * i];

    float m = -1e30f;
#pragma unroll
    for (int i = 0; i < 8; i++)
        m = fmaxf(m, fmaxf(fmaxf(v[i].x, v[i].y), fmaxf(v[i].z, v[i].w)));
    m = warpMax(m);

    float ssum = 0.f;
#pragma unroll
    for (int i = 0; i < 8; i++) {
        v[i].x = __expf(v[i].x - m); v[i].y = __expf(v[i].y - m);
        v[i].z = __expf(v[i].z - m); v[i].w = __expf(v[i].w - m);
        ssum += v[i].x + v[i].y + v[i].z + v[i].w;
    }
    ssum = warpSum(ssum);
    const float inv = 1.f / ssum;

    const float gt = 1.f / (1.f + __expf(-gating[0]));
    const float og = 1.f - gt;

    uint2* AH2 = (uint2*)(AH + (size_t)row * N_);
    uint2* AL2 = (uint2*)(AL + (size_t)row * N_);
    float H = 0.f;
#pragma unroll
    for (int i = 0; i < 8; i++) {
        float4 qv = q4[lane + 32 * i];
        float a[4];
        a[0] = og * v[i].x * inv + gt * qv.x;
        a[1] = og * v[i].y * inv + gt * qv.y;
        a[2] = og * v[i].z * inv + gt * qv.z;
        a[3] = og * v[i].w * inv + gt * qv.w;
        H -= a[0] * __logf(a[0] + 1e-8f) + a[1] * __logf(a[1] + 1e-8f)
           + a[2] * __logf(a[2] + 1e-8f) + a[3] * __logf(a[3] + 1e-8f);
        bf16 h[4], l[4];
#pragma unroll
        for (int j = 0; j < 4; j++) {
            h[j] = __float2bfloat16_rn(a[j]);
            l[j] = __float2bfloat16_rn(a[j] - __bfloat162float(h[j]));
        }
        AH2[lane + 32 * i] = *(uint2*)h;
        AL2[lane + 32 * i] = *(uint2*)l;
    }
    H = warpSum(H);
    if (lane == 0) {
        const float sig = 1.f / (1.f + __expf(-temp[0] * H));
        hmap[row] = 2.f * (1.f - sig);
    }
}

// ---------------- launch ----------------
extern "C" void kernel_launch(void* const* d_in, const int* in_sizes, int n_in,
                              void* d_out, int out_size)
{
    const float* x      = (const float*)d_in[0];
    const float* y      = (const float*)d_in[1];
    const float* coords = (const float*)d_in[2];
    const float* W      = (const float*)d_in[3];
    const float* pe     = (const float*)d_in[4];
    const float* gating = (const float*)d_in[5];
    const float* temp   = (const float*)d_in[6];

    float* out  = (float*)d_out;                // [B,N,D]
    float* hmap = out + (size_t)B_ * N_ * D_;   // [B,N,1]

    float *Sb, *Qb;
    bf16 *xh, *yh, *yl, *wh, *wl, *kh, *kl, *yth, *ytl, *ah, *al;
    cudaGetSymbolAddress((void**)&Sb, g_S);
    cudaGetSymbolAddress((void**)&Qb, g_Q);
    cudaGetSymbolAddress((void**)&xh, g_xh);
    cudaGetSymbolAddress((void**)&yh, g_yh);  cudaGetSymbolAddress((void**)&yl, g_yl);
    cudaGetSymbolAddress((void**)&wh, g_wh);  cudaGetSymbolAddress((void**)&wl, g_wl);
    cudaGetSymbolAddress((void**)&kh, g_kh);  cudaGetSymbolAddress((void**)&kl, g_kl);
    cudaGetSymbolAddress((void**)&yth, g_yth); cudaGetSymbolAddress((void**)&ytl, g_ytl);
    cudaGetSymbolAddress((void**)&ah, g_ah);  cudaGetSymbolAddress((void**)&al, g_al);

    cudaFuncSetAttribute((const void*)gemm_mma<true, 3>,  cudaFuncAttributeMaxDynamicSharedMemorySize, SMEM_BYTES);
    cudaFuncSetAttribute((const void*)gemm_mma<false, 2>, cudaFuncAttributeMaxDynamicSharedMemorySize, SMEM_BYTES);
    cudaFuncSetAttribute((const void*)gemm_mma<false, 3>, cudaFuncAttributeMaxDynamicSharedMemorySize, SMEM_BYTES);

    const int nBND4 = (B_ * N_ * D_) / 4;
    const int nDD4  = (D_ * D_) / 4;

    split_Ty<<<dim3(N_ / 32, D_ / 32, B_), dim3(32, 8)>>>(y, yh, yl, yth, ytl);
    split_h<<<(nBND4 + 255) / 256, 256>>>((const float4*)x, (uint2*)xh, nBND4);
    split_k<<<(nDD4  + 255) / 256, 256>>>((const float4*)W, (uint2*)wh, (uint2*)wl, nDD4);

    pos_kernel<<<N_, 256>>>(coords, pe, Qb);

    // 1) k = y @ W^T  (M=16384, N=768, K=768) -> kh/kl bf16 (coalesced staged epilogue)
    gemm_mma<true, 3><<<dim3(D_ / 128, (B_ * N_) / 128, 1), 128, SMEM_BYTES>>>(
        yh, yl, wh, wl, nullptr, kh, kl, D_, D_, D_, D_, 0, 0, 0, 1.0f);

    // 2) S = (x @ k^T) * SCALE, batched over B -> fp32 (2-term)
    gemm_mma<false, 2><<<dim3(N_ / 128, N_ / 128, B_), 128, SMEM_BYTES>>>(
        xh, xh, kh, kl, Sb, nullptr, nullptr, D_, D_, D_, N_,
        (size_t)N_ * D_, (size_t)N_ * D_, (size_t)N_ * N_, SCALE_);

    // 3) softmax + mix + entropy -> attn bf16 hi/lo + hmap (warp per row)
    mix_kernel<<<(B_ * N_) / 8, 256>>>(Sb, Qb, gating, temp, ah, al, hmap);

    // 4) out = attn @ y (B operand = y^T per batch, K=1024) (3-term)
    gemm_mma<false, 3><<<dim3(D_ / 128, N_ / 128, B_), 128, SMEM_BYTES>>>(
        ah, al, yth, ytl, out, nullptr, nullptr, N_, N_, N_, D_,
        (size_t)N_ * N_, (size_t)D_ * N_, (size_t)N_ * D_, 1.0f);
}

// round 16
// speedup vs baseline: 1.5393x; 1.0032x over previous
#include <cuda_runtime.h>
#include <cuda_bf16.h>
#include <cstdint>

#define B_ 16
#define N_ 1024
#define D_ 768

typedef __nv_bfloat16 bf16;

static const float SCALE_ = 0.03608439182435161f; // 768^-0.5

// ---------------- scratch (device globals: allocation-free contract) ----------------
__device__ __align__(16) float g_S[(size_t)B_ * N_ * N_];   // 64 MB fp32 scores
__device__ __align__(16) float g_Q[(size_t)N_ * N_];        // 4 MB  pos softmax
__device__ __align__(16) bf16 g_xh[(size_t)B_ * N_ * D_];
__device__ __align__(16) bf16 g_yh[(size_t)B_ * N_ * D_], g_yl[(size_t)B_ * N_ * D_];
__device__ __align__(16) bf16 g_wh[(size_t)D_ * D_],      g_wl[(size_t)D_ * D_];
__device__ __align__(16) bf16 g_kh[(size_t)B_ * N_ * D_], g_kl[(size_t)B_ * N_ * D_];
__device__ __align__(16) bf16 g_yth[(size_t)B_ * D_ * N_], g_ytl[(size_t)B_ * D_ * N_];
__device__ __align__(16) bf16 g_ah[(size_t)B_ * N_ * N_],  g_al[(size_t)B_ * N_ * N_];

// ---------------- helpers ----------------
__device__ __forceinline__ uint32_t smem_u32(const void* p) {
    uint32_t a;
    asm("{ .reg .u64 t; cvta.to.shared.u64 t, %1; cvt.u32.u64 %0, t; }" : "=r"(a) : "l"(p));
    return a;
}
#define CP_COMMIT() asm volatile("cp.async.commit_group;" ::: "memory")

__device__ __forceinline__ void mma16816(float* c, const uint32_t* a, const uint32_t* b) {
    asm volatile(
        "mma.sync.aligned.m16n8k16.row.col.f32.bf16.bf16.f32 "
        "{%0,%1,%2,%3}, {%4,%5,%6,%7}, {%8,%9}, {%0,%1,%2,%3};"
        : "+f"(c[0]), "+f"(c[1]), "+f"(c[2]), "+f"(c[3])
        : "r"(a[0]), "r"(a[1]), "r"(a[2]), "r"(a[3]), "r"(b[0]), "r"(b[1]));
}
__device__ __forceinline__ void ldsm4(uint32_t* r, uint32_t addr) {
    asm volatile("ldmatrix.sync.aligned.m8n8.x4.shared.b16 {%0,%1,%2,%3}, [%4];"
        : "=r"(r[0]), "=r"(r[1]), "=r"(r[2]), "=r"(r[3]) : "r"(addr));
}
__device__ __forceinline__ uint32_t packhl(float a, float b, uint32_t& lo) {
    bf16 h0 = __float2bfloat16_rn(a), h1 = __float2bfloat16_rn(b);
    bf16 l0 = __float2bfloat16_rn(a - __bfloat162float(h0));
    bf16 l1 = __float2bfloat16_rn(b - __bfloat162float(h1));
    bf16 pl[2] = {l0, l1};
    lo = *(uint32_t*)pl;
    bf16 ph[2] = {h0, h1};
    return *(uint32_t*)ph;
}

// ---------------- HMMA split-bf16 GEMM (mainloop FROZEN since R10) ----------------
#define TILE_SZ 8192          // 128 * 64
#define SMEM_BYTES 98304      // 96 KB (both variants)

__device__ __forceinline__ void fill_tile(uint32_t dst, const bf16* __restrict__ g,
                                          int ld, int r0, int k0, int tid) {
#pragma unroll
    for (int it = 0; it < 4; it++) {
        int idx = it * 128 + tid;
        int r = idx >> 2, b = idx & 3;
        uint32_t sw = (uint32_t)(r * 64 + ((b ^ ((r >> 1) & 3)) * 16));
        const bf16* src = g + (size_t)(r0 + r) * ld + k0 + b * 8;
        asm volatile("cp.async.cg.shared.global [%0], [%1], 16;"
                     :: "r"(dst + sw), "l"(src));
    }
}

template <int TERMS>
__device__ __forceinline__ void fill_chunk(uint32_t S0,
                                           const bf16* Ah_, const bf16* Al_,
                                           const bf16* Bh_, const bf16* Bl_,
                                           int lda, int ldb, int m0, int n0, int k0, int tid) {
    constexpr int BH = (TERMS == 3) ? 2 : 1;
    fill_tile(S0 + 0 * TILE_SZ, Ah_, lda, m0, k0, tid);
    if (TERMS == 3) fill_tile(S0 + 1 * TILE_SZ, Al_, lda, m0, k0, tid);
    fill_tile(S0 + BH * TILE_SZ,       Bh_, ldb, n0, k0, tid);
    fill_tile(S0 + (BH + 1) * TILE_SZ, Bl_, ldb, n0, k0, tid);
}

template <bool SPLIT_OUT, int TERMS>
__global__ void __launch_bounds__(128, 2) gemm_mma(
    const bf16* __restrict__ Ah_, const bf16* __restrict__ Al_,
    const bf16* __restrict__ Bh_, const bf16* __restrict__ Bl_,
    float* __restrict__ C, bf16* __restrict__ Ch, bf16* __restrict__ Cl,
    int K, int lda, int ldb, int ldc,
    size_t sA, size_t sB, size_t sC, float alpha)
{
    constexpr int NST = (TERMS == 3) ? 3 : 4;
    constexpr int STG = ((TERMS == 3) ? 4 : 3) * TILE_SZ;
    constexpr int BH  = (TERMS == 3) ? 2 : 1;

    extern __shared__ char sm[];
    const uint32_t sb = smem_u32(sm);
    const int tid = threadIdx.x, lane = tid & 31, w = tid >> 5;
    const int wm = w & 1, wn = w >> 1;
    const int g = lane >> 2, tig = lane & 3;
    const int m0 = blockIdx.y * 128, n0 = blockIdx.x * 128;

    Ah_ += (size_t)blockIdx.z * sA; Al_ += (size_t)blockIdx.z * sA;
    Bh_ += (size_t)blockIdx.z * sB; Bl_ += (size_t)blockIdx.z * sB;

    const int rowA = wm * 64 + (lane & 7) + (lane & 8);
    const int hA = (lane >> 4) & 1;
    const int xA = (rowA >> 1) & 3;
    const uint32_t aRow = (uint32_t)(rowA * 64);
    const uint32_t aBlk0 = (uint32_t)(((0 + hA) ^ xA) * 16);
    const uint32_t aBlk1 = (uint32_t)(((2 + hA) ^ xA) * 16);
    const int rowB = wn * 64 + (lane & 7) + ((lane & 16) >> 1);
    const int hB = (lane >> 3) & 1;
    const int xB = (rowB >> 1) & 3;
    const uint32_t bRow = (uint32_t)(rowB * 64);
    const uint32_t bBlk0 = (uint32_t)(((0 + hB) ^ xB) * 16);
    const uint32_t bBlk1 = (uint32_t)(((2 + hB) ^ xB) * 16);

    float acc[4][8][4];
#pragma unroll
    for (int i = 0; i < 4; i++)
#pragma unroll
        for (int j = 0; j < 8; j++)
#pragma unroll
            for (int c = 0; c < 4; c++) acc[i][j][c] = 0.f;

    const int KT = K >> 5;

#pragma unroll
    for (int p = 0; p < NST; p++) {
        fill_chunk<TERMS>(sb + p * STG, Ah_, Al_, Bh_, Bl_, lda, ldb, m0, n0, p * 32, tid);
        CP_COMMIT();
    }

    for (int kt = 0; kt < KT; ++kt) {
        asm volatile("cp.async.wait_group %0;" :: "n"(NST - 2) : "memory");
        __syncthreads();
        const uint32_t S0 = sb + (kt % NST) * STG;
        const uint32_t pAh = S0, pAl = S0 + TILE_SZ;
        const uint32_t pBh = S0 + BH * TILE_SZ, pBl = S0 + (BH + 1) * TILE_SZ;

        uint32_t ah[4][4], al[4][4], bh[8][2], bl[8][2];
#pragma unroll
        for (int mf = 0; mf < 4; mf++) {
            ldsm4(&ah[mf][0], pAh + aRow + mf * 1024 + aBlk0);
            if (TERMS == 3) ldsm4(&al[mf][0], pAl + aRow + mf * 1024 + aBlk0);
        }
#pragma unroll
        for (int p = 0; p < 4; p++) {
            ldsm4(&bh[2 * p][0], pBh + bRow + p * 1024 + bBlk0);
            ldsm4(&bl[2 * p][0], pBl + bRow + p * 1024 + bBlk0);
        }
        if (kt >= 1) {
            if (kt + NST - 1 < KT)
                fill_chunk<TERMS>(sb + ((kt + NST - 1) % NST) * STG,
                                  Ah_, Al_, Bh_, Bl_, lda, ldb, m0, n0,
                                  (kt + NST - 1) * 32, tid);
            CP_COMMIT();
        }
#pragma unroll
        for (int mf = 0; mf < 4; mf++)
#pragma unroll
            for (int nf = 0; nf < 8; nf++)
                mma16816(acc[mf][nf], ah[mf], bh[nf]);
#pragma unroll
        for (int mf = 0; mf < 4; mf++)
#pragma unroll
            for (int nf = 0; nf < 8; nf++)
                mma16816(acc[mf][nf], ah[mf], bl[nf]);
        if (TERMS == 3) {
#pragma unroll
            for (int mf = 0; mf < 4; mf++)
#pragma unroll
                for (int nf = 0; nf < 8; nf++)
                    mma16816(acc[mf][nf], al[mf], bh[nf]);
        }

#pragma unroll
        for (int mf = 0; mf < 4; mf++) {
            ldsm4(&ah[mf][0], pAh + aRow + mf * 1024 + aBlk1);
            if (TERMS == 3) ldsm4(&al[mf][0], pAl + aRow + mf * 1024 + aBlk1);
        }
#pragma unroll
        for (int p = 0; p < 4; p++) {
            ldsm4(&bh[2 * p][0], pBh + bRow + p * 1024 + bBlk1);
            ldsm4(&bl[2 * p][0], pBl + bRow + p * 1024 + bBlk1);
        }
#pragma unroll
        for (int mf = 0; mf < 4; mf++)
#pragma unroll
            for (int nf = 0; nf < 8; nf++)
                mma16816(acc[mf][nf], ah[mf], bh[nf]);
#pragma unroll
        for (int mf = 0; mf < 4; mf++)
#pragma unroll
            for (int nf = 0; nf < 8; nf++)
                mma16816(acc[mf][nf], ah[mf], bl[nf]);
        if (TERMS == 3) {
#pragma unroll
            for (int mf = 0; mf < 4; mf++)
#pragma unroll
                for (int nf = 0; nf < 8; nf++)
                    mma16816(acc[mf][nf], al[mf], bh[nf]);
        }
    }

    // ---------------- epilogue ----------------
    if (SPLIT_OUT) {
        // Stage each mf-slice (32 rows x 128 cols, hi+lo) through SMEM; write with
        // coalesced 16B uint4 stores (full 32B sectors). Rows padded to 272B.
        const uint32_t hiB = sb, loB = sb + 32 * 272;
#pragma unroll
        for (int mf = 0; mf < 4; mf++) {
            __syncthreads();
            const uint32_t s0 = (uint32_t)((wm * 16 + g) * 272);
            const uint32_t s1 = (uint32_t)((wm * 16 + g + 8) * 272);
#pragma unroll
            for (int nf = 0; nf < 8; nf++) {
                const uint32_t cb = (uint32_t)(wn * 128 + nf * 16 + tig * 4);
                uint32_t lo0, lo1;
                uint32_t hi0 = packhl(acc[mf][nf][0] * alpha, acc[mf][nf][1] * alpha, lo0);
                uint32_t hi1 = packhl(acc[mf][nf][2] * alpha, acc[mf][nf][3] * alpha, lo1);
                *(uint32_t*)(sm + (hiB - sb) + s0 + cb) = hi0;
                *(uint32_t*)(sm + (hiB - sb) + s1 + cb) = hi1;
                *(uint32_t*)(sm + (loB - sb) + s0 + cb) = lo0;
                *(uint32_t*)(sm + (loB - sb) + s1 + cb) = lo1;
            }
            __syncthreads();
#pragma unroll
            for (int it = 0; it < 8; it++) {
                const int chunk = it * 128 + tid;
                const int isLo = chunk >> 9;
                const int c2 = chunk & 511;
                const int r = c2 >> 4, cs = c2 & 15;
                uint4 val = *(const uint4*)(sm + (isLo ? (loB - sb) : 0) + r * 272 + cs * 16);
                const int grow = m0 + (r >> 4) * 64 + mf * 16 + (r & 15);
                bf16* dst = isLo ? Cl : Ch;
                *(uint4*)&dst[(size_t)grow * ldc + n0 + cs * 8] = val;
            }
        }
    } else {
#pragma unroll
        for (int mf = 0; mf < 4; mf++) {
#pragma unroll
            for (int nf = 0; nf < 8; nf++) {
                const int row = m0 + wm * 64 + mf * 16 + g;
                const int col = n0 + wn * 64 + nf * 8 + tig * 2;
                float c0 = acc[mf][nf][0] * alpha, c1 = acc[mf][nf][1] * alpha;
                float c2 = acc[mf][nf][2] * alpha, c3 = acc[mf][nf][3] * alpha;
                float* Cp = C + (size_t)blockIdx.z * sC;
                float2 v0 = {c0, c1}, v2 = {c2, c3};
                *(float2*)&Cp[(size_t)row * ldc + col]       = v0;
                *(float2*)&Cp[(size_t)(row + 8) * ldc + col] = v2;
            }
        }
    }
}

// -------- fused input split: blocks [0, nX) -> x hi-only; [nX, nX+nW) -> W hi/lo -----
__global__ void __launch_bounds__(256) split_xw(
    const float4* __restrict__ x, uint2* __restrict__ xh, int nX4,
    const float4* __restrict__ Wm, uint2* __restrict__ wh, uint2* __restrict__ wl, int nW4,
    int nXblocks)
{
    if ((int)blockIdx.x < nXblocks) {
        int i = blockIdx.x * 256 + threadIdx.x;
        if (i >= nX4) return;
        float4 v = x[i];
        float xs[4] = {v.x, v.y, v.z, v.w};
        bf16 h[4];
#pragma unroll
        for (int j = 0; j < 4; j++) h[j] = __float2bfloat16_rn(xs[j]);
        xh[i] = *(uint2*)h;
    } else {
        int i = (blockIdx.x - nXblocks) * 256 + threadIdx.x;
        if (i >= nW4) return;
        float4 v = Wm[i];
        float xs[4] = {v.x, v.y, v.z, v.w};
        bf16 h[4], l[4];
#pragma unroll
        for (int j = 0; j < 4; j++) {
            h[j] = __float2bfloat16_rn(xs[j]);
            l[j] = __float2bfloat16_rn(xs[j] - __bfloat162float(h[j]));
        }
        wh[i] = *(uint2*)h;
        wl[i] = *(uint2*)l;
    }
}

// ------- y [B,N,D]: split to yh/yl AND transposed yth/ytl [B,D,N] in one pass -------
__global__ void __launch_bounds__(256) split_Ty(const float* __restrict__ y,
                                                bf16* __restrict__ yh, bf16* __restrict__ yl,
                                                bf16* __restrict__ th, bf16* __restrict__ tl) {
    __shared__ float t[32][33];
    const int b = blockIdx.z;
    const float* Y = y + (size_t)b * N_ * D_;
    const int n0 = blockIdx.x * 32, d0 = blockIdx.y * 32;
    const int tx = threadIdx.x, ty = threadIdx.y;  // (32, 8)
    bf16* YH = yh + (size_t)b * N_ * D_;
    bf16* YL = yl + (size_t)b * N_ * D_;
#pragma unroll
    for (int i = 0; i < 4; i++) {
        const int r = ty + i * 8;
        const float v = Y[(size_t)(n0 + r) * D_ + d0 + tx];
        t[r][tx] = v;
        bf16 h = __float2bfloat16_rn(v);
        YH[(size_t)(n0 + r) * D_ + d0 + tx] = h;
        YL[(size_t)(n0 + r) * D_ + d0 + tx] = __float2bfloat16_rn(v - __bfloat162float(h));
    }
    __syncthreads();
    bf16* TH = th + (size_t)b * D_ * N_;
    bf16* TL = tl + (size_t)b * D_ * N_;
#pragma unroll
    for (int i = 0; i < 4; i++) {
        int r = ty + i * 8;
        float v = t[tx][r];
        bf16 h = __float2bfloat16_rn(v);
        TH[(size_t)(d0 + r) * N_ + n0 + tx] = h;
        TL[(size_t)(d0 + r) * N_ + n0 + tx] = __float2bfloat16_rn(v - __bfloat162float(h));
    }
}

// ---------------- reductions ----------------
__device__ __forceinline__ float warpMax(float v) {
#pragma unroll
    for (int o = 16; o; o >>= 1) v = fmaxf(v, __shfl_xor_sync(0xffffffffu, v, o));
    return v;
}
__device__ __forceinline__ float warpSum(float v) {
#pragma unroll
    for (int o = 16; o; o >>= 1) v += __shfl_xor_sync(0xffffffffu, v, o);
    return v;
}

// ---------------- positional softmax ----------------
__global__ void __launch_bounds__(256) pos_kernel(
    const float* __restrict__ coords, const float* __restrict__ pe, float* __restrict__ Q)
{
    __shared__ float pesh[6];
    __shared__ float red[8], red2[8];
    const int p = blockIdx.x;
    const int tid = threadIdx.x;
    if (tid < 6) pesh[tid] = pe[p * 6 + tid];
    __syncthreads();

    const float* cbase = coords + (size_t)p * N_ * 6;
    float z[4];
#pragma unroll
    for (int i = 0; i < 4; i++) {
        const float* c = cbase + (size_t)(i * 256 + tid) * 6;
        float2 c01 = *(const float2*)(c);
        float2 c23 = *(const float2*)(c + 2);
        float2 c45 = *(const float2*)(c + 4);
        z[i] = c01.x * pesh[0] + c01.y * pesh[1] + c23.x * pesh[2]
             + c23.y * pesh[3] + c45.x * pesh[4] + c45.y * pesh[5];
    }
    float m = fmaxf(fmaxf(z[0], z[1]), fmaxf(z[2], z[3]));
    m = warpMax(m);
    if ((tid & 31) == 0) red[tid >> 5] = m;
    __syncthreads();
    m = red[0];
#pragma unroll
    for (int i = 1; i < 8; i++) m = fmaxf(m, red[i]);

    float e[4], s = 0.f;
#pragma unroll
    for (int i = 0; i < 4; i++) { e[i] = __expf(z[i] - m); s += e[i]; }
    s = warpSum(s);
    if ((tid & 31) == 0) red2[tid >> 5] = s;
    __syncthreads();
    s = red2[0];
#pragma unroll
    for (int i = 1; i < 8; i++) s += red2[i];
    const float inv = 1.f / s;
#pragma unroll
    for (int i = 0; i < 4; i++)
        Q[(size_t)p * N_ + i * 256 + tid] = e[i] * inv;
}

// -------- row softmax + gate mix + entropy; warp per row; attn -> bf16 hi/lo --------
__global__ void __launch_bounds__(256) mix_kernel(
    const float* __restrict__ S, const float* __restrict__ Q,
    const float* __restrict__ gating, const float* __restrict__ temp,
    bf16* __restrict__ AH, bf16* __restrict__ AL, float* __restrict__ hmap)
{
    const int row  = blockIdx.x * 8 + (threadIdx.x >> 5);   // b*N + n
    const int lane = threadIdx.x & 31;
    const float4* s4 = (const float4*)(S + (size_t)row * N_);
    const float4* q4 = (const float4*)(Q + (size_t)(row & (N_ - 1)) * N_);

    float4 v[8];
#pragma unroll
    for (int i = 0; i < 8; i++) v[i] = s4[lane + 32 * i];

    float m = -1e30f;
#pragma unroll
    for (int i = 0; i < 8; i++)
        m = fmaxf(m, fmaxf(fmaxf(v[i].x, v[i].y), fmaxf(v[i].z, v[i].w)));
    m = warpMax(m);

    float ssum = 0.f;
#pragma unroll
    for (int i = 0; i < 8; i++) {
        v[i].x = __expf(v[i].x - m); v[i].y = __expf(v[i].y - m);
        v[i].z = __expf(v[i].z - m); v[i].w = __expf(v[i].w - m);
        ssum += v[i].x + v[i].y + v[i].z + v[i].w;
    }
    ssum = warpSum(ssum);
    const float inv = 1.f / ssum;

    const float gt = 1.f / (1.f + __expf(-gating[0]));
    const float og = 1.f - gt;

    uint2* AH2 = (uint2*)(AH + (size_t)row * N_);
    uint2* AL2 = (uint2*)(AL + (size_t)row * N_);
    float H = 0.f;
#pragma unroll
    for (int i = 0; i < 8; i++) {
        float4 qv = q4[lane + 32 * i];
        float a[4];
        a[0] = og * v[i].x * inv + gt * qv.x;
        a[1] = og * v[i].y * inv + gt * qv.y;
        a[2] = og * v[i].z * inv + gt * qv.z;
        a[3] = og * v[i].w * inv + gt * qv.w;
        H -= a[0] * __logf(a[0] + 1e-8f) + a[1] * __logf(a[1] + 1e-8f)
           + a[2] * __logf(a[2] + 1e-8f) + a[3] * __logf(a[3] + 1e-8f);
        bf16 h[4], l[4];
#pragma unroll
        for (int j = 0; j < 4; j++) {
            h[j] = __float2bfloat16_rn(a[j]);
            l[j] = __float2bfloat16_rn(a[j] - __bfloat162float(h[j]));
        }
        AH2[lane + 32 * i] = *(uint2*)h;
        AL2[lane + 32 * i] = *(uint2*)l;
    }
    H = warpSum(H);
    if (lane == 0) {
        const float sig = 1.f / (1.f + __expf(-temp[0] * H));
        hmap[row] = 2.f * (1.f - sig);
    }
}

// ---------------- launch ----------------
extern "C" void kernel_launch(void* const* d_in, const int* in_sizes, int n_in,
                              void* d_out, int out_size)
{
    const float* x      = (const float*)d_in[0];
    const float* y      = (const float*)d_in[1];
    const float* coords = (const float*)d_in[2];
    const float* W      = (const float*)d_in[3];
    const float* pe     = (const float*)d_in[4];
    const float* gating = (const float*)d_in[5];
    const float* temp   = (const float*)d_in[6];

    float* out  = (float*)d_out;                // [B,N,D]
    float* hmap = out + (size_t)B_ * N_ * D_;   // [B,N,1]

    float *Sb, *Qb;
    bf16 *xh, *yh, *yl, *wh, *wl, *kh, *kl, *yth, *ytl, *ah, *al;
    cudaGetSymbolAddress((void**)&Sb, g_S);
    cudaGetSymbolAddress((void**)&Qb, g_Q);
    cudaGetSymbolAddress((void**)&xh, g_xh);
    cudaGetSymbolAddress((void**)&yh, g_yh);  cudaGetSymbolAddress((void**)&yl, g_yl);
    cudaGetSymbolAddress((void**)&wh, g_wh);  cudaGetSymbolAddress((void**)&wl, g_wl);
    cudaGetSymbolAddress((void**)&kh, g_kh);  cudaGetSymbolAddress((void**)&kl, g_kl);
    cudaGetSymbolAddress((void**)&yth, g_yth); cudaGetSymbolAddress((void**)&ytl, g_ytl);
    cudaGetSymbolAddress((void**)&ah, g_ah);  cudaGetSymbolAddress((void**)&al, g_al);

    cudaFuncSetAttribute((const void*)gemm_mma<true, 3>,  cudaFuncAttributeMaxDynamicSharedMemorySize, SMEM_BYTES);
    cudaFuncSetAttribute((const void*)gemm_mma<false, 2>, cudaFuncAttributeMaxDynamicSharedMemorySize, SMEM_BYTES);
    cudaFuncSetAttribute((const void*)gemm_mma<false, 3>, cudaFuncAttributeMaxDynamicSharedMemorySize, SMEM_BYTES);

    const int nX4 = (B_ * N_ * D_) / 4;
    const int nW4 = (D_ * D_) / 4;
    const int nXblocks = (nX4 + 255) / 256;
    const int nWblocks = (nW4 + 255) / 256;

    split_Ty<<<dim3(N_ / 32, D_ / 32, B_), dim3(32, 8)>>>(y, yh, yl, yth, ytl);
    split_xw<<<nXblocks + nWblocks, 256>>>(
        (const float4*)x, (uint2*)xh, nX4,
        (const float4*)W, (uint2*)wh, (uint2*)wl, nW4, nXblocks);

    pos_kernel<<<N_, 256>>>(coords, pe, Qb);

    // 1) k = y @ W^T  (M=16384, N=768, K=768) -> kh/kl bf16 (coalesced staged epilogue)
    gemm_mma<true, 3><<<dim3(D_ / 128, (B_ * N_) / 128, 1), 128, SMEM_BYTES>>>(
        yh, yl, wh, wl, nullptr, kh, kl, D_, D_, D_, D_, 0, 0, 0, 1.0f);

    // 2) S = (x @ k^T) * SCALE, batched over B -> fp32 (2-term)
    gemm_mma<false, 2><<<dim3(N_ / 128, N_ / 128, B_), 128, SMEM_BYTES>>>(
        xh, xh, kh, kl, Sb, nullptr, nullptr, D_, D_, D_, N_,
        (size_t)N_ * D_, (size_t)N_ * D_, (size_t)N_ * N_, SCALE_);

    // 3) softmax + mix + entropy -> attn bf16 hi/lo + hmap (warp per row)
    mix_kernel<<<(B_ * N_) / 8, 256>>>(Sb, Qb, gating, temp, ah, al, hmap);

    // 4) out = attn @ y (B operand = y^T per batch, K=1024) (3-term)
    gemm_mma<false, 3><<<dim3(D_ / 128, N_ / 128, B_), 128, SMEM_BYTES>>>(
        ah, al, yth, ytl, out, nullptr, nullptr, N_, N_, N_, D_,
        (size_t)N_ * N_, (size_t)D_ * N_, (size_t)N_ * D_, 1.0f);
}

// round 17
// speedup vs baseline: 1.5460x; 1.0044x over previous
#include <cuda_runtime.h>
#include <cuda_bf16.h>
#include <cstdint>

#define B_ 16
#define N_ 1024
#define D_ 768

typedef __nv_bfloat16 bf16;

static const float SCALE_ = 0.03608439182435161f; // 768^-0.5

// ---------------- scratch (device globals: allocation-free contract) ----------------
__device__ __align__(16) float g_S[(size_t)B_ * N_ * N_];   // 64 MB fp32 scores
__device__ __align__(16) float g_Q[(size_t)N_ * N_];        // 4 MB  pos softmax
__device__ __align__(16) bf16 g_xh[(size_t)B_ * N_ * D_];
__device__ __align__(16) bf16 g_yh[(size_t)B_ * N_ * D_], g_yl[(size_t)B_ * N_ * D_];
__device__ __align__(16) bf16 g_wh[(size_t)D_ * D_],      g_wl[(size_t)D_ * D_];
__device__ __align__(16) bf16 g_kh[(size_t)B_ * N_ * D_], g_kl[(size_t)B_ * N_ * D_];
__device__ __align__(16) bf16 g_yth[(size_t)B_ * D_ * N_], g_ytl[(size_t)B_ * D_ * N_];
__device__ __align__(16) bf16 g_ah[(size_t)B_ * N_ * N_],  g_al[(size_t)B_ * N_ * N_];

// ---------------- helpers ----------------
__device__ __forceinline__ uint32_t smem_u32(const void* p) {
    uint32_t a;
    asm("{ .reg .u64 t; cvta.to.shared.u64 t, %1; cvt.u32.u64 %0, t; }" : "=r"(a) : "l"(p));
    return a;
}
#define CP_COMMIT() asm volatile("cp.async.commit_group;" ::: "memory")

__device__ __forceinline__ void mma16816(float* c, const uint32_t* a, const uint32_t* b) {
    asm volatile(
        "mma.sync.aligned.m16n8k16.row.col.f32.bf16.bf16.f32 "
        "{%0,%1,%2,%3}, {%4,%5,%6,%7}, {%8,%9}, {%0,%1,%2,%3};"
        : "+f"(c[0]), "+f"(c[1]), "+f"(c[2]), "+f"(c[3])
        : "r"(a[0]), "r"(a[1]), "r"(a[2]), "r"(a[3]), "r"(b[0]), "r"(b[1]));
}
__device__ __forceinline__ void ldsm4(uint32_t* r, uint32_t addr) {
    asm volatile("ldmatrix.sync.aligned.m8n8.x4.shared.b16 {%0,%1,%2,%3}, [%4];"
        : "=r"(r[0]), "=r"(r[1]), "=r"(r[2]), "=r"(r[3]) : "r"(addr));
}
__device__ __forceinline__ uint32_t packhl(float a, float b, uint32_t& lo) {
    bf16 h0 = __float2bfloat16_rn(a), h1 = __float2bfloat16_rn(b);
    bf16 l0 = __float2bfloat16_rn(a - __bfloat162float(h0));
    bf16 l1 = __float2bfloat16_rn(b - __bfloat162float(h1));
    bf16 pl[2] = {l0, l1};
    lo = *(uint32_t*)pl;
    bf16 ph[2] = {h0, h1};
    return *(uint32_t*)ph;
}

// ---------------- HMMA split-bf16 GEMM (mainloop FROZEN since R10) ----------------
#define TILE_SZ 8192          // 128 * 64
#define SMEM_BYTES 98304      // 96 KB (both variants)

__device__ __forceinline__ void fill_tile(uint32_t dst, const bf16* __restrict__ g,
                                          int ld, int r0, int k0, int tid) {
#pragma unroll
    for (int it = 0; it < 4; it++) {
        int idx = it * 128 + tid;
        int r = idx >> 2, b = idx & 3;
        uint32_t sw = (uint32_t)(r * 64 + ((b ^ ((r >> 1) & 3)) * 16));
        const bf16* src = g + (size_t)(r0 + r) * ld + k0 + b * 8;
        asm volatile("cp.async.cg.shared.global [%0], [%1], 16;"
                     :: "r"(dst + sw), "l"(src));
    }
}

template <int TERMS>
__device__ __forceinline__ void fill_chunk(uint32_t S0,
                                           const bf16* Ah_, const bf16* Al_,
                                           const bf16* Bh_, const bf16* Bl_,
                                           int lda, int ldb, int m0, int n0, int k0, int tid) {
    constexpr int BH = (TERMS == 3) ? 2 : 1;
    fill_tile(S0 + 0 * TILE_SZ, Ah_, lda, m0, k0, tid);
    if (TERMS == 3) fill_tile(S0 + 1 * TILE_SZ, Al_, lda, m0, k0, tid);
    fill_tile(S0 + BH * TILE_SZ,       Bh_, ldb, n0, k0, tid);
    fill_tile(S0 + (BH + 1) * TILE_SZ, Bl_, ldb, n0, k0, tid);
}

template <bool SPLIT_OUT, int TERMS>
__global__ void __launch_bounds__(128, 2) gemm_mma(
    const bf16* __restrict__ Ah_, const bf16* __restrict__ Al_,
    const bf16* __restrict__ Bh_, const bf16* __restrict__ Bl_,
    float* __restrict__ C, bf16* __restrict__ Ch, bf16* __restrict__ Cl,
    int K, int lda, int ldb, int ldc,
    size_t sA, size_t sB, size_t sC, float alpha)
{
    constexpr int NST = (TERMS == 3) ? 3 : 4;
    constexpr int STG = ((TERMS == 3) ? 4 : 3) * TILE_SZ;
    constexpr int BH  = (TERMS == 3) ? 2 : 1;

    extern __shared__ char sm[];
    const uint32_t sb = smem_u32(sm);
    const int tid = threadIdx.x, lane = tid & 31, w = tid >> 5;
    const int wm = w & 1, wn = w >> 1;
    const int g = lane >> 2, tig = lane & 3;
    const int m0 = blockIdx.y * 128, n0 = blockIdx.x * 128;

    Ah_ += (size_t)blockIdx.z * sA; Al_ += (size_t)blockIdx.z * sA;
    Bh_ += (size_t)blockIdx.z * sB; Bl_ += (size_t)blockIdx.z * sB;

    const int rowA = wm * 64 + (lane & 7) + (lane & 8);
    const int hA = (lane >> 4) & 1;
    const int xA = (rowA >> 1) & 3;
    const uint32_t aRow = (uint32_t)(rowA * 64);
    const uint32_t aBlk0 = (uint32_t)(((0 + hA) ^ xA) * 16);
    const uint32_t aBlk1 = (uint32_t)(((2 + hA) ^ xA) * 16);
    const int rowB = wn * 64 + (lane & 7) + ((lane & 16) >> 1);
    const int hB = (lane >> 3) & 1;
    const int xB = (rowB >> 1) & 3;
    const uint32_t bRow = (uint32_t)(rowB * 64);
    const uint32_t bBlk0 = (uint32_t)(((0 + hB) ^ xB) * 16);
    const uint32_t bBlk1 = (uint32_t)(((2 + hB) ^ xB) * 16);

    float acc[4][8][4];
#pragma unroll
    for (int i = 0; i < 4; i++)
#pragma unroll
        for (int j = 0; j < 8; j++)
#pragma unroll
            for (int c = 0; c < 4; c++) acc[i][j][c] = 0.f;

    const int KT = K >> 5;

#pragma unroll
    for (int p = 0; p < NST; p++) {
        fill_chunk<TERMS>(sb + p * STG, Ah_, Al_, Bh_, Bl_, lda, ldb, m0, n0, p * 32, tid);
        CP_COMMIT();
    }

    for (int kt = 0; kt < KT; ++kt) {
        asm volatile("cp.async.wait_group %0;" :: "n"(NST - 2) : "memory");
        __syncthreads();
        const uint32_t S0 = sb + (kt % NST) * STG;
        const uint32_t pAh = S0, pAl = S0 + TILE_SZ;
        const uint32_t pBh = S0 + BH * TILE_SZ, pBl = S0 + (BH + 1) * TILE_SZ;

        uint32_t ah[4][4], al[4][4], bh[8][2], bl[8][2];
#pragma unroll
        for (int mf = 0; mf < 4; mf++) {
            ldsm4(&ah[mf][0], pAh + aRow + mf * 1024 + aBlk0);
            if (TERMS == 3) ldsm4(&al[mf][0], pAl + aRow + mf * 1024 + aBlk0);
        }
#pragma unroll
        for (int p = 0; p < 4; p++) {
            ldsm4(&bh[2 * p][0], pBh + bRow + p * 1024 + bBlk0);
            ldsm4(&bl[2 * p][0], pBl + bRow + p * 1024 + bBlk0);
        }
        if (kt >= 1) {
            if (kt + NST - 1 < KT)
                fill_chunk<TERMS>(sb + ((kt + NST - 1) % NST) * STG,
                                  Ah_, Al_, Bh_, Bl_, lda, ldb, m0, n0,
                                  (kt + NST - 1) * 32, tid);
            CP_COMMIT();
        }
#pragma unroll
        for (int mf = 0; mf < 4; mf++)
#pragma unroll
            for (int nf = 0; nf < 8; nf++)
                mma16816(acc[mf][nf], ah[mf], bh[nf]);
#pragma unroll
        for (int mf = 0; mf < 4; mf++)
#pragma unroll
            for (int nf = 0; nf < 8; nf++)
                mma16816(acc[mf][nf], ah[mf], bl[nf]);
        if (TERMS == 3) {
#pragma unroll
            for (int mf = 0; mf < 4; mf++)
#pragma unroll
                for (int nf = 0; nf < 8; nf++)
                    mma16816(acc[mf][nf], al[mf], bh[nf]);
        }

#pragma unroll
        for (int mf = 0; mf < 4; mf++) {
            ldsm4(&ah[mf][0], pAh + aRow + mf * 1024 + aBlk1);
            if (TERMS == 3) ldsm4(&al[mf][0], pAl + aRow + mf * 1024 + aBlk1);
        }
#pragma unroll
        for (int p = 0; p < 4; p++) {
            ldsm4(&bh[2 * p][0], pBh + bRow + p * 1024 + bBlk1);
            ldsm4(&bl[2 * p][0], pBl + bRow + p * 1024 + bBlk1);
        }
#pragma unroll
        for (int mf = 0; mf < 4; mf++)
#pragma unroll
            for (int nf = 0; nf < 8; nf++)
                mma16816(acc[mf][nf], ah[mf], bh[nf]);
#pragma unroll
        for (int mf = 0; mf < 4; mf++)
#pragma unroll
            for (int nf = 0; nf < 8; nf++)
                mma16816(acc[mf][nf], ah[mf], bl[nf]);
        if (TERMS == 3) {
#pragma unroll
            for (int mf = 0; mf < 4; mf++)
#pragma unroll
                for (int nf = 0; nf < 8; nf++)
                    mma16816(acc[mf][nf], al[mf], bh[nf]);
        }
    }

    // ---------------- epilogue ----------------
    if (SPLIT_OUT) {
        const uint32_t hiB = sb, loB = sb + 32 * 272;
#pragma unroll
        for (int mf = 0; mf < 4; mf++) {
            __syncthreads();
            const uint32_t s0 = (uint32_t)((wm * 16 + g) * 272);
            const uint32_t s1 = (uint32_t)((wm * 16 + g + 8) * 272);
#pragma unroll
            for (int nf = 0; nf < 8; nf++) {
                const uint32_t cb = (uint32_t)(wn * 128 + nf * 16 + tig * 4);
                uint32_t lo0, lo1;
                uint32_t hi0 = packhl(acc[mf][nf][0] * alpha, acc[mf][nf][1] * alpha, lo0);
                uint32_t hi1 = packhl(acc[mf][nf][2] * alpha, acc[mf][nf][3] * alpha, lo1);
                *(uint32_t*)(sm + (hiB - sb) + s0 + cb) = hi0;
                *(uint32_t*)(sm + (hiB - sb) + s1 + cb) = hi1;
                *(uint32_t*)(sm + (loB - sb) + s0 + cb) = lo0;
                *(uint32_t*)(sm + (loB - sb) + s1 + cb) = lo1;
            }
            __syncthreads();
#pragma unroll
            for (int it = 0; it < 8; it++) {
                const int chunk = it * 128 + tid;
                const int isLo = chunk >> 9;
                const int c2 = chunk & 511;
                const int r = c2 >> 4, cs = c2 & 15;
                uint4 val = *(const uint4*)(sm + (isLo ? (loB - sb) : 0) + r * 272 + cs * 16);
                const int grow = m0 + (r >> 4) * 64 + mf * 16 + (r & 15);
                bf16* dst = isLo ? Cl : Ch;
                *(uint4*)&dst[(size_t)grow * ldc + n0 + cs * 8] = val;
            }
        }
    } else {
#pragma unroll
        for (int mf = 0; mf < 4; mf++) {
#pragma unroll
            for (int nf = 0; nf < 8; nf++) {
                const int row = m0 + wm * 64 + mf * 16 + g;
                const int col = n0 + wn * 64 + nf * 8 + tig * 2;
                float c0 = acc[mf][nf][0] * alpha, c1 = acc[mf][nf][1] * alpha;
                float c2 = acc[mf][nf][2] * alpha, c3 = acc[mf][nf][3] * alpha;
                float* Cp = C + (size_t)blockIdx.z * sC;
                float2 v0 = {c0, c1}, v2 = {c2, c3};
                *(float2*)&Cp[(size_t)row * ldc + col]       = v0;
                *(float2*)&Cp[(size_t)(row + 8) * ldc + col] = v2;
            }
        }
    }
}

// ---------------- reductions ----------------
__device__ __forceinline__ float warpMax(float v) {
#pragma unroll
    for (int o = 16; o; o >>= 1) v = fmaxf(v, __shfl_xor_sync(0xffffffffu, v, o));
    return v;
}
__device__ __forceinline__ float warpSum(float v) {
#pragma unroll
    for (int o = 16; o; o >>= 1) v += __shfl_xor_sync(0xffffffffu, v, o);
    return v;
}

// ---- fused prep: blocks [0,nX) x hi-split; [nX,nX+nW) W hi/lo split;
//      [nX+nW, nX+nW+N_) positional softmax row p ----
__global__ void __launch_bounds__(256) split_xw_pos(
    const float4* __restrict__ x, uint2* __restrict__ xh, int nX4,
    const float4* __restrict__ Wm, uint2* __restrict__ wh, uint2* __restrict__ wl, int nW4,
    const float* __restrict__ coords, const float* __restrict__ pe, float* __restrict__ Q,
    int nXblocks, int nWblocks)
{
    const int bx = (int)blockIdx.x;
    if (bx < nXblocks) {
        int i = bx * 256 + threadIdx.x;
        if (i >= nX4) return;
        float4 v = x[i];
        float xs[4] = {v.x, v.y, v.z, v.w};
        bf16 h[4];
#pragma unroll
        for (int j = 0; j < 4; j++) h[j] = __float2bfloat16_rn(xs[j]);
        xh[i] = *(uint2*)h;
    } else if (bx < nXblocks + nWblocks) {
        int i = (bx - nXblocks) * 256 + threadIdx.x;
        if (i >= nW4) return;
        float4 v = Wm[i];
        float xs[4] = {v.x, v.y, v.z, v.w};
        bf16 h[4], l[4];
#pragma unroll
        for (int j = 0; j < 4; j++) {
            h[j] = __float2bfloat16_rn(xs[j]);
            l[j] = __float2bfloat16_rn(xs[j] - __bfloat162float(h[j]));
        }
        wh[i] = *(uint2*)h;
        wl[i] = *(uint2*)l;
    } else {
        __shared__ float pesh[6];
        __shared__ float red[8], red2[8];
        const int p = bx - nXblocks - nWblocks;
        const int tid = threadIdx.x;
        if (tid < 6) pesh[tid] = pe[p * 6 + tid];
        __syncthreads();

        const float* cbase = coords + (size_t)p * N_ * 6;
        float z[4];
#pragma unroll
        for (int i = 0; i < 4; i++) {
            const float* c = cbase + (size_t)(i * 256 + tid) * 6;
            float2 c01 = *(const float2*)(c);
            float2 c23 = *(const float2*)(c + 2);
            float2 c45 = *(const float2*)(c + 4);
            z[i] = c01.x * pesh[0] + c01.y * pesh[1] + c23.x * pesh[2]
                 + c23.y * pesh[3] + c45.x * pesh[4] + c45.y * pesh[5];
        }
        float m = fmaxf(fmaxf(z[0], z[1]), fmaxf(z[2], z[3]));
        m = warpMax(m);
        if ((tid & 31) == 0) red[tid >> 5] = m;
        __syncthreads();
        m = red[0];
#pragma unroll
        for (int i = 1; i < 8; i++) m = fmaxf(m, red[i]);

        float e[4], s = 0.f;
#pragma unroll
        for (int i = 0; i < 4; i++) { e[i] = __expf(z[i] - m); s += e[i]; }
        s = warpSum(s);
        if ((tid & 31) == 0) red2[tid >> 5] = s;
        __syncthreads();
        s = red2[0];
#pragma unroll
        for (int i = 1; i < 8; i++) s += red2[i];
        const float inv = 1.f / s;
#pragma unroll
        for (int i = 0; i < 4; i++)
            Q[(size_t)p * N_ + i * 256 + tid] = e[i] * inv;
    }
}

// ------- y [B,N,D]: split to yh/yl AND transposed yth/ytl [B,D,N] in one pass -------
__global__ void __launch_bounds__(256) split_Ty(const float* __restrict__ y,
                                                bf16* __restrict__ yh, bf16* __restrict__ yl,
                                                bf16* __restrict__ th, bf16* __restrict__ tl) {
    __shared__ float t[32][33];
    const int b = blockIdx.z;
    const float* Y = y + (size_t)b * N_ * D_;
    const int n0 = blockIdx.x * 32, d0 = blockIdx.y * 32;
    const int tx = threadIdx.x, ty = threadIdx.y;  // (32, 8)
    bf16* YH = yh + (size_t)b * N_ * D_;
    bf16* YL = yl + (size_t)b * N_ * D_;
#pragma unroll
    for (int i = 0; i < 4; i++) {
        const int r = ty + i * 8;
        const float v = Y[(size_t)(n0 + r) * D_ + d0 + tx];
        t[r][tx] = v;
        bf16 h = __float2bfloat16_rn(v);
        YH[(size_t)(n0 + r) * D_ + d0 + tx] = h;
        YL[(size_t)(n0 + r) * D_ + d0 + tx] = __float2bfloat16_rn(v - __bfloat162float(h));
    }
    __syncthreads();
    bf16* TH = th + (size_t)b * D_ * N_;
    bf16* TL = tl + (size_t)b * D_ * N_;
#pragma unroll
    for (int i = 0; i < 4; i++) {
        int r = ty + i * 8;
        float v = t[tx][r];
        bf16 h = __float2bfloat16_rn(v);
        TH[(size_t)(d0 + r) * N_ + n0 + tx] = h;
        TL[(size_t)(d0 + r) * N_ + n0 + tx] = __float2bfloat16_rn(v - __bfloat162float(h));
    }
}

// -------- row softmax + gate mix + entropy; warp per row; attn -> bf16 hi/lo --------
__global__ void __launch_bounds__(256) mix_kernel(
    const float* __restrict__ S, const float* __restrict__ Q,
    const float* __restrict__ gating, const float* __restrict__ temp,
    bf16* __restrict__ AH, bf16* __restrict__ AL, float* __restrict__ hmap)
{
    const int row  = blockIdx.x * 8 + (threadIdx.x >> 5);   // b*N + n
    const int lane = threadIdx.x & 31;
    const float4* s4 = (const float4*)(S + (size_t)row * N_);
    const float4* q4 = (const float4*)(Q + (size_t)(row & (N_ - 1)) * N_);

    float4 v[8];
#pragma unroll
    for (int i = 0; i < 8; i++) v[i] = s4[lane + 32 * i];

    float m = -1e30f;
#pragma unroll
    for (int i = 0; i < 8; i++)
        m = fmaxf(m, fmaxf(fmaxf(v[i].x, v[i].y), fmaxf(v[i].z, v[i].w)));
    m = warpMax(m);

    float ssum = 0.f;
#pragma unroll
    for (int i = 0; i < 8; i++) {
        v[i].x = __expf(v[i].x - m); v[i].y = __expf(v[i].y - m);
        v[i].z = __expf(v[i].z - m); v[i].w = __expf(v[i].w - m);
        ssum += v[i].x + v[i].y + v[i].z + v[i].w;
    }
    ssum = warpSum(ssum);
    const float inv = 1.f / ssum;

    const float gt = 1.f / (1.f + __expf(-gating[0]));
    const float og = 1.f - gt;

    uint2* AH2 = (uint2*)(AH + (size_t)row * N_);
    uint2* AL2 = (uint2*)(AL + (size_t)row * N_);
    float H = 0.f;
#pragma unroll
    for (int i = 0; i < 8; i++) {
        float4 qv = q4[lane + 32 * i];
        float a[4];
        a[0] = og * v[i].x * inv + gt * qv.x;
        a[1] = og * v[i].y * inv + gt * qv.y;
        a[2] = og * v[i].z * inv + gt * qv.z;
        a[3] = og * v[i].w * inv + gt * qv.w;
        H -= a[0] * __logf(a[0] + 1e-8f) + a[1] * __logf(a[1] + 1e-8f)
           + a[2] * __logf(a[2] + 1e-8f) + a[3] * __logf(a[3] + 1e-8f);
        bf16 h[4], l[4];
#pragma unroll
        for (int j = 0; j < 4; j++) {
            h[j] = __float2bfloat16_rn(a[j]);
            l[j] = __float2bfloat16_rn(a[j] - __bfloat162float(h[j]));
        }
        AH2[lane + 32 * i] = *(uint2*)h;
        AL2[lane + 32 * i] = *(uint2*)l;
    }
    H = warpSum(H);
    if (lane == 0) {
        const float sig = 1.f / (1.f + __expf(-temp[0] * H));
        hmap[row] = 2.f * (1.f - sig);
    }
}

// ---------------- launch ----------------
extern "C" void kernel_launch(void* const* d_in, const int* in_sizes, int n_in,
                              void* d_out, int out_size)
{
    const float* x      = (const float*)d_in[0];
    const float* y      = (const float*)d_in[1];
    const float* coords = (const float*)d_in[2];
    const float* W      = (const float*)d_in[3];
    const float* pe     = (const float*)d_in[4];
    const float* gating = (const float*)d_in[5];
    const float* temp   = (const float*)d_in[6];

    float* out  = (float*)d_out;                // [B,N,D]
    float* hmap = out + (size_t)B_ * N_ * D_;   // [B,N,1]

    float *Sb, *Qb;
    bf16 *xh, *yh, *yl, *wh, *wl, *kh, *kl, *yth, *ytl, *ah, *al;
    cudaGetSymbolAddress((void**)&Sb, g_S);
    cudaGetSymbolAddress((void**)&Qb, g_Q);
    cudaGetSymbolAddress((void**)&xh, g_xh);
    cudaGetSymbolAddress((void**)&yh, g_yh);  cudaGetSymbolAddress((void**)&yl, g_yl);
    cudaGetSymbolAddress((void**)&wh, g_wh);  cudaGetSymbolAddress((void**)&wl, g_wl);
    cudaGetSymbolAddress((void**)&kh, g_kh);  cudaGetSymbolAddress((void**)&kl, g_kl);
    cudaGetSymbolAddress((void**)&yth, g_yth); cudaGetSymbolAddress((void**)&ytl, g_ytl);
    cudaGetSymbolAddress((void**)&ah, g_ah);  cudaGetSymbolAddress((void**)&al, g_al);

    cudaFuncSetAttribute((const void*)gemm_mma<true, 3>,  cudaFuncAttributeMaxDynamicSharedMemorySize, SMEM_BYTES);
    cudaFuncSetAttribute((const void*)gemm_mma<false, 2>, cudaFuncAttributeMaxDynamicSharedMemorySize, SMEM_BYTES);
    cudaFuncSetAttribute((const void*)gemm_mma<false, 3>, cudaFuncAttributeMaxDynamicSharedMemorySize, SMEM_BYTES);

    const int nX4 = (B_ * N_ * D_) / 4;
    const int nW4 = (D_ * D_) / 4;
    const int nXblocks = (nX4 + 255) / 256;
    const int nWblocks = (nW4 + 255) / 256;

    split_Ty<<<dim3(N_ / 32, D_ / 32, B_), dim3(32, 8)>>>(y, yh, yl, yth, ytl);
    split_xw_pos<<<nXblocks + nWblocks + N_, 256>>>(
        (const float4*)x, (uint2*)xh, nX4,
        (const float4*)W, (uint2*)wh, (uint2*)wl, nW4,
        coords, pe, Qb, nXblocks, nWblocks);

    // 1) k = y @ W^T  (M=16384, N=768, K=768) -> kh/kl bf16 (coalesced staged epilogue)
    gemm_mma<true, 3><<<dim3(D_ / 128, (B_ * N_) / 128, 1), 128, SMEM_BYTES>>>(
        yh, yl, wh, wl, nullptr, kh, kl, D_, D_, D_, D_, 0, 0, 0, 1.0f);

    // 2) S = (x @ k^T) * SCALE, batched over B -> fp32 (2-term)
    gemm_mma<false, 2><<<dim3(N_ / 128, N_ / 128, B_), 128, SMEM_BYTES>>>(
        xh, xh, kh, kl, Sb, nullptr, nullptr, D_, D_, D_, N_,
        (size_t)N_ * D_, (size_t)N_ * D_, (size_t)N_ * N_, SCALE_);

    // 3) softmax + mix + entropy -> attn bf16 hi/lo + hmap (warp per row)
    mix_kernel<<<(B_ * N_) / 8, 256>>>(Sb, Qb, gating, temp, ah, al, hmap);

    // 4) out = attn @ y (B operand = y^T per batch, K=1024) (3-term)
    gemm_mma<false, 3><<<dim3(D_ / 128, N_ / 128, B_), 128, SMEM_BYTES>>>(
        ah, al, yth, ytl, out, nullptr, nullptr, N_, N_, N_, D_,
        (size_t)N_ * N_, (size_t)D_ * N_, (size_t)N_ * D_, 1.0f);
}